// round 12
// baseline (speedup 1.0000x reference)
#include <cuda_runtime.h>
#include <cuda_bf16.h>
#include <cstdint>
#include <stdint.h>
#include <math.h>

// Problem constants
#define BB 2
#define TT 2048
#define CC 2048
#define HH 16
#define HD 128
#define MLPD 8192
#define BT (BB*TT)          // 4096 rows
#define EPS 1e-5f

// ---------------------------------------------------------------------------
// Scratch (device globals; no allocations allowed)
// ---------------------------------------------------------------------------
__device__ float g_q[(size_t)BT*CC];
__device__ float g_k[(size_t)BT*CC];
__device__ float g_v[(size_t)BT*CC];
__device__ float g_x1[(size_t)BT*CC];

// bf16 hi/lo split operands
__device__ __nv_bfloat16 g_hH[(size_t)BT*CC],  g_hL[(size_t)BT*CC];
__device__ __nv_bfloat16 g_attH[(size_t)BT*CC], g_attL[(size_t)BT*CC];
__device__ __nv_bfloat16 g_mH[(size_t)BT*MLPD], g_mL[(size_t)BT*MLPD];
__device__ __nv_bfloat16 g_wqH[(size_t)CC*CC],  g_wqL[(size_t)CC*CC];
__device__ __nv_bfloat16 g_wkH[(size_t)CC*CC],  g_wkL[(size_t)CC*CC];
__device__ __nv_bfloat16 g_wvH[(size_t)CC*CC],  g_wvL[(size_t)CC*CC];
__device__ __nv_bfloat16 g_woH[(size_t)CC*CC],  g_woL[(size_t)CC*CC];
__device__ __nv_bfloat16 g_fc1H[(size_t)MLPD*CC], g_fc1L[(size_t)MLPD*CC];
__device__ __nv_bfloat16 g_fc2H[(size_t)MLPD*CC], g_fc2L[(size_t)MLPD*CC];

// ---------------------------------------------------------------------------
// Helpers
// ---------------------------------------------------------------------------
union Pack4 { __nv_bfloat16 h[4]; uint2 u; };

__device__ __forceinline__ uint32_t smem_u32(const void* p) {
    uint32_t a;
    asm("{ .reg .u64 t; cvta.to.shared.u64 t, %1; cvt.u32.u64 %0, t; }" : "=r"(a) : "l"(p));
    return a;
}

__device__ __forceinline__ void cpasync16(uint32_t dst, const void* src) {
    asm volatile("cp.async.cg.shared.global [%0], [%1], 16;" :: "r"(dst), "l"(src));
}
#define CP_COMMIT() asm volatile("cp.async.commit_group;" ::: "memory")
#define CP_WAIT(n)  asm volatile("cp.async.wait_group %0;" :: "n"(n) : "memory")

#define MMA_BF16(d, a, b0v, b1v)                                           \
    asm volatile("mma.sync.aligned.m16n8k16.row.col.f32.bf16.bf16.f32 "    \
        "{%0,%1,%2,%3}, {%4,%5,%6,%7}, {%8,%9}, {%0,%1,%2,%3};"            \
        : "+f"(d[0]), "+f"(d[1]), "+f"(d[2]), "+f"(d[3])                   \
        : "r"(a[0]), "r"(a[1]), "r"(a[2]), "r"(a[3]), "r"(b0v), "r"(b1v))

__device__ __forceinline__ void split_pack2(float x, float y,
                                            unsigned int& hi, unsigned int& lo) {
    __nv_bfloat16 xh = __float2bfloat16_rn(x);
    __nv_bfloat16 yh = __float2bfloat16_rn(y);
    __nv_bfloat16 xl = __float2bfloat16_rn(x - __bfloat162float(xh));
    __nv_bfloat16 yl = __float2bfloat16_rn(y - __bfloat162float(yh));
    hi = (unsigned int)__bfloat16_as_ushort(xh) |
         ((unsigned int)__bfloat16_as_ushort(yh) << 16);
    lo = (unsigned int)__bfloat16_as_ushort(xl) |
         ((unsigned int)__bfloat16_as_ushort(yl) << 16);
}

// ---------------------------------------------------------------------------
// Elementwise fp32 -> (hi, lo) bf16 split
// ---------------------------------------------------------------------------
__global__ void split_fp32(const float* __restrict__ in,
                           __nv_bfloat16* __restrict__ H,
                           __nv_bfloat16* __restrict__ L, int n4) {
    int i = blockIdx.x * blockDim.x + threadIdx.x;
    if (i >= n4) return;
    float4 v = reinterpret_cast<const float4*>(in)[i];
    float f[4] = {v.x, v.y, v.z, v.w};
    Pack4 Hp, Lp;
    #pragma unroll
    for (int j = 0; j < 4; j++) {
        __nv_bfloat16 hv = __float2bfloat16_rn(f[j]);
        Hp.h[j] = hv;
        Lp.h[j] = __float2bfloat16_rn(f[j] - __bfloat162float(hv));
    }
    reinterpret_cast<uint2*>(H)[i] = Hp.u;
    reinterpret_cast<uint2*>(L)[i] = Lp.u;
}

// ---------------------------------------------------------------------------
// RMSNorm with split epilogue
// ---------------------------------------------------------------------------
__global__ void rmsnorm_split_kernel(const float* __restrict__ x,
                                     __nv_bfloat16* __restrict__ H,
                                     __nv_bfloat16* __restrict__ L) {
    int row = blockIdx.x;
    const float* xr = x + (size_t)row * CC;
    float ss = 0.f;
    for (int c = threadIdx.x; c < CC; c += blockDim.x) {
        float vv = xr[c];
        ss += vv * vv;
    }
    __shared__ float red[32];
    #pragma unroll
    for (int off = 16; off; off >>= 1) ss += __shfl_xor_sync(0xffffffffu, ss, off);
    int wid = threadIdx.x >> 5, lane = threadIdx.x & 31;
    if (lane == 0) red[wid] = ss;
    __syncthreads();
    if (wid == 0) {
        float v2 = lane < (blockDim.x >> 5) ? red[lane] : 0.f;
        #pragma unroll
        for (int off = 16; off; off >>= 1) v2 += __shfl_xor_sync(0xffffffffu, v2, off);
        if (lane == 0) red[0] = rsqrtf(v2 / (float)CC + EPS);
    }
    __syncthreads();
    float r = red[0];
    size_t base = (size_t)row * CC;
    for (int c = threadIdx.x * 2; c < CC; c += blockDim.x * 2) {
        float a = xr[c] * r, b = xr[c + 1] * r;
        unsigned int hi, lo;
        split_pack2(a, b, hi, lo);
        *reinterpret_cast<unsigned int*>(&H[base + c]) = hi;
        *reinterpret_cast<unsigned int*>(&L[base + c]) = lo;
    }
}

// ---------------------------------------------------------------------------
// bf16x3 GEMM, pre-split operands, cp.async 3-stage pipeline.
// Block 128x128x32, 128 threads = 4 warps, warp tile 64x64 (2x2 warp grid).
// Halves smem crossbar traffic vs 32x32 warp tiles.
// ---------------------------------------------------------------------------
enum { EPI_F32 = 0, EPI_ADDF = 1, EPI_RELU2S = 2 };

#define GP_PART   10240              // bytes per part (128 rows x 80B pitch)
#define GP_STAGE  (4*GP_PART)        // AH,AL,BH,BL
#define GP_NSTG   3
#define GP_SMEM   (GP_NSTG*GP_STAGE) // 122880 bytes

__device__ __forceinline__ void gp_issue(
    uint32_t sb32, int buf, int tid,
    const __nv_bfloat16* __restrict__ AH, const __nv_bfloat16* __restrict__ AL,
    const __nv_bfloat16* __restrict__ BH, const __nv_bfloat16* __restrict__ BL,
    int bm, int bn, int K, int k0)
{
    int row = tid;                    // 0..127
    size_t offA = (size_t)(bm + row) * K + k0;
    size_t offB = (size_t)(bn + row) * K + k0;
    uint32_t d = sb32 + buf * GP_STAGE + row * 80;
    #pragma unroll
    for (int c = 0; c < 4; c++) {
        cpasync16(d + c * 16,               AH + offA + c * 8);
        cpasync16(d + c * 16 + GP_PART,     AL + offA + c * 8);
        cpasync16(d + c * 16 + 2 * GP_PART, BH + offB + c * 8);
        cpasync16(d + c * 16 + 3 * GP_PART, BL + offB + c * 8);
    }
}

template <int EPI>
__global__ __launch_bounds__(128, 1) void gemm_pre(
    const __nv_bfloat16* __restrict__ AH, const __nv_bfloat16* __restrict__ AL,
    const __nv_bfloat16* __restrict__ BH, const __nv_bfloat16* __restrict__ BL,
    const float* __restrict__ Res, float* __restrict__ C,
    __nv_bfloat16* __restrict__ CH, __nv_bfloat16* __restrict__ CL,
    int M, int N, int K)
{
    extern __shared__ char smp[];
    uint32_t sb32 = smem_u32(smp);
    int tid = threadIdx.x;
    int bm = blockIdx.y * 128;
    int bn = blockIdx.x * 128;
    int wid = tid >> 5, lane = tid & 31;
    int wm = (wid & 1) * 64;          // warp m offset
    int wn = (wid >> 1) * 64;         // warp n offset
    int lt = lane >> 2, g = lane & 3;

    float acc[4][8][4];
    #pragma unroll
    for (int i = 0; i < 4; i++)
        #pragma unroll
        for (int j = 0; j < 8; j++)
            #pragma unroll
            for (int r = 0; r < 4; r++) acc[i][j][r] = 0.f;

    int nst = K / 32;
    #pragma unroll
    for (int p = 0; p < 2; p++) {
        gp_issue(sb32, p, tid, AH, AL, BH, BL, bm, bn, K, p * 32);
        CP_COMMIT();
    }

    for (int it = 0; it < nst; it++) {
        if (it + 1 < nst) { CP_WAIT(1); } else { CP_WAIT(0); }
        __syncthreads();

        int b = it - (it / 3) * 3;   // it % 3
        const unsigned int* base =
            reinterpret_cast<const unsigned int*>(smp + b * GP_STAGE);
        const unsigned int* AHw = base;
        const unsigned int* ALw = base + 2560;
        const unsigned int* BHw = base + 5120;
        const unsigned int* BLw = base + 7680;

        #pragma unroll
        for (int kk2 = 0; kk2 < 2; kk2++) {
            int kw = kk2 * 8;
            unsigned int ah[4][4], al[4][4];
            #pragma unroll
            for (int mi = 0; mi < 4; mi++) {
                int m0 = wm + mi * 16 + lt;
                int base0 = m0 * 20 + kw + g;
                int base1 = base0 + 160;          // +8 rows
                ah[mi][0] = AHw[base0];
                ah[mi][1] = AHw[base1];
                ah[mi][2] = AHw[base0 + 4];
                ah[mi][3] = AHw[base1 + 4];
                al[mi][0] = ALw[base0];
                al[mi][1] = ALw[base1];
                al[mi][2] = ALw[base0 + 4];
                al[mi][3] = ALw[base1 + 4];
            }
            #pragma unroll
            for (int ni = 0; ni < 8; ni++) {
                int n0 = wn + ni * 8 + lt;
                int nb = n0 * 20 + kw + g;
                unsigned int bh0 = BHw[nb], bh1 = BHw[nb + 4];
                unsigned int bl0 = BLw[nb], bl1 = BLw[nb + 4];
                #pragma unroll
                for (int mi = 0; mi < 4; mi++) {
                    MMA_BF16(acc[mi][ni], ah[mi], bh0, bh1);
                    MMA_BF16(acc[mi][ni], ah[mi], bl0, bl1);
                    MMA_BF16(acc[mi][ni], al[mi], bh0, bh1);
                }
            }
        }

        if (it + 2 < nst) {
            int nb3 = (it + 2) - ((it + 2) / 3) * 3;
            gp_issue(sb32, nb3, tid, AH, AL, BH, BL, bm, bn, K, (it + 2) * 32);
            CP_COMMIT();
        }
    }

    // epilogue
    #pragma unroll
    for (int mi = 0; mi < 4; mi++) {
        #pragma unroll
        for (int ni = 0; ni < 8; ni++) {
            int r0 = bm + wm + mi * 16 + lt;
            int c0 = bn + wn + ni * 8 + g * 2;
            float2 v0 = {acc[mi][ni][0], acc[mi][ni][1]};
            float2 v1 = {acc[mi][ni][2], acc[mi][ni][3]};
            if (EPI == EPI_RELU2S) {
                v0.x = fmaxf(v0.x, 0.f); v0.x *= v0.x;
                v0.y = fmaxf(v0.y, 0.f); v0.y *= v0.y;
                v1.x = fmaxf(v1.x, 0.f); v1.x *= v1.x;
                v1.y = fmaxf(v1.y, 0.f); v1.y *= v1.y;
                unsigned int h0, l0, h1, l1;
                split_pack2(v0.x, v0.y, h0, l0);
                split_pack2(v1.x, v1.y, h1, l1);
                *reinterpret_cast<unsigned int*>(&CH[(size_t)r0 * N + c0]) = h0;
                *reinterpret_cast<unsigned int*>(&CL[(size_t)r0 * N + c0]) = l0;
                *reinterpret_cast<unsigned int*>(&CH[(size_t)(r0 + 8) * N + c0]) = h1;
                *reinterpret_cast<unsigned int*>(&CL[(size_t)(r0 + 8) * N + c0]) = l1;
            } else {
                if (EPI == EPI_ADDF) {
                    float2 r0v = *reinterpret_cast<const float2*>(&Res[(size_t)r0 * N + c0]);
                    float2 r1v = *reinterpret_cast<const float2*>(&Res[(size_t)(r0 + 8) * N + c0]);
                    v0.x += r0v.x; v0.y += r0v.y;
                    v1.x += r1v.x; v1.y += r1v.y;
                }
                *reinterpret_cast<float2*>(&C[(size_t)r0 * N + c0]) = v0;
                *reinterpret_cast<float2*>(&C[(size_t)(r0 + 8) * N + c0]) = v1;
            }
        }
    }
}

// ---------------------------------------------------------------------------
// bf16x3 flash attention via mma.sync (proven R9/R10 version)
// ---------------------------------------------------------------------------
#define AQH 0
#define AQL 8704
#define AKH 17408
#define AKL 26112
#define AVH 34816
#define AVL 44032
#define ATT_SMEM 106496   // bytes
#define WQH 0
#define WQL 4352
#define WKH 8704
#define WKL 13056
#define WVH 17408
#define WVL 22016

__global__ __launch_bounds__(128) void attn_mma(
    const float* __restrict__ q, const float* __restrict__ k,
    const float* __restrict__ v,
    __nv_bfloat16* __restrict__ oH, __nv_bfloat16* __restrict__ oL)
{
    extern __shared__ char attsm[];
    __nv_bfloat16* sb = reinterpret_cast<__nv_bfloat16*>(attsm);
    unsigned int* s32 = reinterpret_cast<unsigned int*>(attsm);

    int tid = threadIdx.x;
    int wid = tid >> 5, lane = tid & 31;
    int lt = lane >> 2, g = lane & 3;
    int wrow = wid * 16;
    int qt = blockIdx.x, h = blockIdx.y, b = blockIdx.z;
    int qb = qt * 64;
    const float scale = 0.08838834764831845f;  // 1/sqrt(128)
    size_t base = ((size_t)b * TT) * CC + (size_t)h * HD;

    #pragma unroll
    for (int i = 0; i < 16; i++) {
        int lin = tid + i * 128;
        int r = lin >> 5, c4 = (lin & 31) * 4;
        float4 vq = *reinterpret_cast<const float4*>(&q[base + (size_t)(qb + r) * CC + c4]);
        float f[4] = {vq.x * scale, vq.y * scale, vq.z * scale, vq.w * scale};
        Pack4 H, L;
        #pragma unroll
        for (int j = 0; j < 4; j++) {
            __nv_bfloat16 hv = __float2bfloat16_rn(f[j]);
            H.h[j] = hv;
            L.h[j] = __float2bfloat16_rn(f[j] - __bfloat162float(hv));
        }
        *reinterpret_cast<uint2*>(&sb[AQH + r * 136 + c4]) = H.u;
        *reinterpret_cast<uint2*>(&sb[AQL + r * 136 + c4]) = L.u;
    }

    float oacc[16][4];
    #pragma unroll
    for (int i = 0; i < 16; i++)
        #pragma unroll
        for (int j = 0; j < 4; j++) oacc[i][j] = 0.f;
    float m0 = -1e30f, m1 = -1e30f, l0 = 0.f, l1 = 0.f;

    for (int nt = 0; nt <= qt; nt++) {
        int kb = nt * 64;
        #pragma unroll
        for (int i = 0; i < 16; i++) {
            int lin = tid + i * 128;
            int r = lin >> 5, c4 = (lin & 31) * 4;
            float4 vk = *reinterpret_cast<const float4*>(&k[base + (size_t)(kb + r) * CC + c4]);
            float f[4] = {vk.x, vk.y, vk.z, vk.w};
            Pack4 H, L;
            #pragma unroll
            for (int j = 0; j < 4; j++) {
                __nv_bfloat16 hv = __float2bfloat16_rn(f[j]);
                H.h[j] = hv;
                L.h[j] = __float2bfloat16_rn(f[j] - __bfloat162float(hv));
            }
            *reinterpret_cast<uint2*>(&sb[AKH + r * 136 + c4]) = H.u;
            *reinterpret_cast<uint2*>(&sb[AKL + r * 136 + c4]) = L.u;
        }
        #pragma unroll
        for (int i = 0; i < 16; i++) {
            int lin = tid + i * 128;
            int r = lin & 63;
            int c4 = ((lin >> 6) & 31) * 4;
            float4 vv = *reinterpret_cast<const float4*>(&v[base + (size_t)(kb + r) * CC + c4]);
            float f[4] = {vv.x, vv.y, vv.z, vv.w};
            #pragma unroll
            for (int j = 0; j < 4; j++) {
                __nv_bfloat16 hv = __float2bfloat16_rn(f[j]);
                sb[AVH + (c4 + j) * 72 + r] = hv;
                sb[AVL + (c4 + j) * 72 + r] = __float2bfloat16_rn(f[j] - __bfloat162float(hv));
            }
        }
        __syncthreads();

        float sacc[8][4];
        #pragma unroll
        for (int i = 0; i < 8; i++)
            #pragma unroll
            for (int j = 0; j < 4; j++) sacc[i][j] = 0.f;

        #pragma unroll
        for (int ks = 0; ks < 8; ks++) {
            unsigned int aH[4], aL[4];
            int ab = (wrow + lt) * 68 + ks * 8 + g;
            aH[0] = s32[WQH + ab];       aH[1] = s32[WQH + ab + 544];
            aH[2] = s32[WQH + ab + 4];   aH[3] = s32[WQH + ab + 548];
            aL[0] = s32[WQL + ab];       aL[1] = s32[WQL + ab + 544];
            aL[2] = s32[WQL + ab + 4];   aL[3] = s32[WQL + ab + 548];
            #pragma unroll
            for (int ni = 0; ni < 8; ni++) {
                int bb = (ni * 8 + lt) * 68 + ks * 8 + g;
                unsigned int bh0 = s32[WKH + bb], bh1 = s32[WKH + bb + 4];
                unsigned int bl0 = s32[WKL + bb], bl1 = s32[WKL + bb + 4];
                MMA_BF16(sacc[ni], aH, bh0, bh1);
                MMA_BF16(sacc[ni], aH, bl0, bl1);
                MMA_BF16(sacc[ni], aL, bh0, bh1);
            }
        }

        if (nt == qt) {
            int row0 = qb + wrow + lt, row1 = row0 + 8;
            #pragma unroll
            for (int ni = 0; ni < 8; ni++) {
                int c0 = kb + ni * 8 + 2 * g;
                if (c0 > row0)     sacc[ni][0] = -1e30f;
                if (c0 + 1 > row0) sacc[ni][1] = -1e30f;
                if (c0 > row1)     sacc[ni][2] = -1e30f;
                if (c0 + 1 > row1) sacc[ni][3] = -1e30f;
            }
        }

        float rm0 = -1e30f, rm1 = -1e30f;
        #pragma unroll
        for (int ni = 0; ni < 8; ni++) {
            rm0 = fmaxf(rm0, fmaxf(sacc[ni][0], sacc[ni][1]));
            rm1 = fmaxf(rm1, fmaxf(sacc[ni][2], sacc[ni][3]));
        }
        rm0 = fmaxf(rm0, __shfl_xor_sync(0xffffffffu, rm0, 1));
        rm0 = fmaxf(rm0, __shfl_xor_sync(0xffffffffu, rm0, 2));
        rm1 = fmaxf(rm1, __shfl_xor_sync(0xffffffffu, rm1, 1));
        rm1 = fmaxf(rm1, __shfl_xor_sync(0xffffffffu, rm1, 2));
        float mn0 = fmaxf(m0, rm0), mn1 = fmaxf(m1, rm1);
        float al0 = __expf(m0 - mn0), al1 = __expf(m1 - mn1);
        m0 = mn0; m1 = mn1;
        float rs0 = 0.f, rs1 = 0.f;
        #pragma unroll
        for (int ni = 0; ni < 8; ni++) {
            sacc[ni][0] = __expf(sacc[ni][0] - m0);
            sacc[ni][1] = __expf(sacc[ni][1] - m0);
            sacc[ni][2] = __expf(sacc[ni][2] - m1);
            sacc[ni][3] = __expf(sacc[ni][3] - m1);
            rs0 += sacc[ni][0] + sacc[ni][1];
            rs1 += sacc[ni][2] + sacc[ni][3];
        }
        l0 = l0 * al0 + rs0;
        l1 = l1 * al1 + rs1;
        #pragma unroll
        for (int ni = 0; ni < 16; ni++) {
            oacc[ni][0] *= al0; oacc[ni][1] *= al0;
            oacc[ni][2] *= al1; oacc[ni][3] *= al1;
        }

        #pragma unroll
        for (int kk = 0; kk < 4; kk++) {
            unsigned int pH[4], pL[4];
            split_pack2(sacc[2 * kk][0],     sacc[2 * kk][1],     pH[0], pL[0]);
            split_pack2(sacc[2 * kk][2],     sacc[2 * kk][3],     pH[1], pL[1]);
            split_pack2(sacc[2 * kk + 1][0], sacc[2 * kk + 1][1], pH[2], pL[2]);
            split_pack2(sacc[2 * kk + 1][2], sacc[2 * kk + 1][3], pH[3], pL[3]);
            #pragma unroll
            for (int ni = 0; ni < 16; ni++) {
                int vb2 = (ni * 8 + lt) * 36 + kk * 8 + g;
                unsigned int vh0 = s32[WVH + vb2], vh1 = s32[WVH + vb2 + 4];
                unsigned int vl0 = s32[WVL + vb2], vl1 = s32[WVL + vb2 + 4];
                MMA_BF16(oacc[ni], pH, vh0, vh1);
                MMA_BF16(oacc[ni], pH, vl0, vl1);
                MMA_BF16(oacc[ni], pL, vh0, vh1);
            }
        }
        __syncthreads();
    }

    l0 += __shfl_xor_sync(0xffffffffu, l0, 1);
    l0 += __shfl_xor_sync(0xffffffffu, l0, 2);
    l1 += __shfl_xor_sync(0xffffffffu, l1, 1);
    l1 += __shfl_xor_sync(0xffffffffu, l1, 2);
    float inv0 = 1.f / l0, inv1 = 1.f / l1;
    int row0 = qb + wrow + lt;
    #pragma unroll
    for (int ni = 0; ni < 16; ni++) {
        size_t o0 = base + (size_t)row0 * CC + ni * 8 + 2 * g;
        size_t o1 = o0 + (size_t)8 * CC;
        unsigned int h0, l0u, h1, l1u;
        split_pack2(oacc[ni][0] * inv0, oacc[ni][1] * inv0, h0, l0u);
        split_pack2(oacc[ni][2] * inv1, oacc[ni][3] * inv1, h1, l1u);
        *reinterpret_cast<unsigned int*>(&oH[o0]) = h0;
        *reinterpret_cast<unsigned int*>(&oL[o0]) = l0u;
        *reinterpret_cast<unsigned int*>(&oH[o1]) = h1;
        *reinterpret_cast<unsigned int*>(&oL[o1]) = l1u;
    }
}

// ---------------------------------------------------------------------------
// Launch
// ---------------------------------------------------------------------------
extern "C" void kernel_launch(void* const* d_in, const int* in_sizes, int n_in,
                              void* d_out, int out_size) {
    const float* x   = (const float*)d_in[0];
    const float* wq  = (const float*)d_in[1];
    const float* wk  = (const float*)d_in[2];
    const float* wv  = (const float*)d_in[3];
    const float* wo  = (const float*)d_in[4];
    const float* fc1 = (const float*)d_in[5];
    const float* fc2 = (const float*)d_in[6];
    float* out = (float*)d_out;

    float *q, *k, *v, *x1;
    cudaGetSymbolAddress((void**)&q,  g_q);
    cudaGetSymbolAddress((void**)&k,  g_k);
    cudaGetSymbolAddress((void**)&v,  g_v);
    cudaGetSymbolAddress((void**)&x1, g_x1);

    __nv_bfloat16 *hH, *hL, *attH, *attL, *mH, *mL;
    __nv_bfloat16 *wqH, *wqL, *wkH, *wkL, *wvH, *wvL, *woH, *woL;
    __nv_bfloat16 *fc1H, *fc1L, *fc2H, *fc2L;
    cudaGetSymbolAddress((void**)&hH, g_hH);     cudaGetSymbolAddress((void**)&hL, g_hL);
    cudaGetSymbolAddress((void**)&attH, g_attH); cudaGetSymbolAddress((void**)&attL, g_attL);
    cudaGetSymbolAddress((void**)&mH, g_mH);     cudaGetSymbolAddress((void**)&mL, g_mL);
    cudaGetSymbolAddress((void**)&wqH, g_wqH);   cudaGetSymbolAddress((void**)&wqL, g_wqL);
    cudaGetSymbolAddress((void**)&wkH, g_wkH);   cudaGetSymbolAddress((void**)&wkL, g_wkL);
    cudaGetSymbolAddress((void**)&wvH, g_wvH);   cudaGetSymbolAddress((void**)&wvL, g_wvL);
    cudaGetSymbolAddress((void**)&woH, g_woH);   cudaGetSymbolAddress((void**)&woL, g_woL);
    cudaGetSymbolAddress((void**)&fc1H, g_fc1H); cudaGetSymbolAddress((void**)&fc1L, g_fc1L);
    cudaGetSymbolAddress((void**)&fc2H, g_fc2H); cudaGetSymbolAddress((void**)&fc2L, g_fc2L);

    cudaFuncSetAttribute(attn_mma, cudaFuncAttributeMaxDynamicSharedMemorySize, ATT_SMEM);
    cudaFuncSetAttribute(gemm_pre<EPI_F32>,    cudaFuncAttributeMaxDynamicSharedMemorySize, GP_SMEM);
    cudaFuncSetAttribute(gemm_pre<EPI_ADDF>,   cudaFuncAttributeMaxDynamicSharedMemorySize, GP_SMEM);
    cudaFuncSetAttribute(gemm_pre<EPI_RELU2S>, cudaFuncAttributeMaxDynamicSharedMemorySize, GP_SMEM);

    // 0) split weights
    {
        int n4w = CC * CC / 4;
        int n4f = MLPD * CC / 4;
        split_fp32<<<(n4w + 255) / 256, 256>>>(wq, wqH, wqL, n4w);
        split_fp32<<<(n4w + 255) / 256, 256>>>(wk, wkH, wkL, n4w);
        split_fp32<<<(n4w + 255) / 256, 256>>>(wv, wvH, wvL, n4w);
        split_fp32<<<(n4w + 255) / 256, 256>>>(wo, woH, woL, n4w);
        split_fp32<<<(n4f + 255) / 256, 256>>>(fc1, fc1H, fc1L, n4f);
        split_fp32<<<(n4f + 255) / 256, 256>>>(fc2, fc2H, fc2L, n4f);
    }

    // 1) h = rmsnorm(x)  (split)
    rmsnorm_split_kernel<<<BT, 256>>>(x, hH, hL);

    // 2-4) q,k,v = h @ w^T  (fp32 out for attention)
    dim3 thr(128);
    dim3 g_qkv(CC / 128, BT / 128);
    gemm_pre<EPI_F32><<<g_qkv, thr, GP_SMEM>>>(hH, hL, wqH, wqL, nullptr, q, nullptr, nullptr, BT, CC, CC);
    gemm_pre<EPI_F32><<<g_qkv, thr, GP_SMEM>>>(hH, hL, wkH, wkL, nullptr, k, nullptr, nullptr, BT, CC, CC);
    gemm_pre<EPI_F32><<<g_qkv, thr, GP_SMEM>>>(hH, hL, wvH, wvL, nullptr, v, nullptr, nullptr, BT, CC, CC);

    // 5) causal attention -> split att
    dim3 g_att_grid(TT / 64, HH, BB);
    attn_mma<<<g_att_grid, 128, ATT_SMEM>>>(q, k, v, attH, attL);

    // 6) x1 = x + att @ wo^T
    gemm_pre<EPI_ADDF><<<g_qkv, thr, GP_SMEM>>>(attH, attL, woH, woL, x, x1, nullptr, nullptr, BT, CC, CC);

    // 7) h = rmsnorm(x1)  (split)
    rmsnorm_split_kernel<<<BT, 256>>>(x1, hH, hL);

    // 8) m = relu(h @ fc1^T)^2  (split out)
    dim3 g_fc1(MLPD / 128, BT / 128);
    gemm_pre<EPI_RELU2S><<<g_fc1, thr, GP_SMEM>>>(hH, hL, fc1H, fc1L, nullptr, nullptr, mH, mL, BT, MLPD, CC);

    // 9) out = x1 + m @ fc2^T
    dim3 g_fc2(CC / 128, BT / 128);
    gemm_pre<EPI_ADDF><<<g_fc2, thr, GP_SMEM>>>(mH, mL, fc2H, fc2L, x1, out, nullptr, nullptr, BT, CC, MLPD);
}

// round 15
// speedup vs baseline: 1.2447x; 1.2447x over previous
#include <cuda_runtime.h>
#include <cuda_bf16.h>
#include <cstdint>
#include <stdint.h>
#include <math.h>

// Problem constants
#define BB 2
#define TT 2048
#define CC 2048
#define HH 16
#define HD 128
#define MLPD 8192
#define BT (BB*TT)          // 4096 rows
#define EPS 1e-5f

// ---------------------------------------------------------------------------
// Scratch (device globals; no allocations allowed)
// ---------------------------------------------------------------------------
__device__ float g_q[(size_t)BT*CC];
__device__ float g_k[(size_t)BT*CC];
__device__ float g_v[(size_t)BT*CC];
__device__ float g_x1[(size_t)BT*CC];

// bf16 hi/lo split operands
__device__ __nv_bfloat16 g_hH[(size_t)BT*CC],  g_hL[(size_t)BT*CC];
__device__ __nv_bfloat16 g_attH[(size_t)BT*CC], g_attL[(size_t)BT*CC];
__device__ __nv_bfloat16 g_mH[(size_t)BT*MLPD], g_mL[(size_t)BT*MLPD];
__device__ __nv_bfloat16 g_wqH[(size_t)CC*CC],  g_wqL[(size_t)CC*CC];
__device__ __nv_bfloat16 g_wkH[(size_t)CC*CC],  g_wkL[(size_t)CC*CC];
__device__ __nv_bfloat16 g_wvH[(size_t)CC*CC],  g_wvL[(size_t)CC*CC];
__device__ __nv_bfloat16 g_woH[(size_t)CC*CC],  g_woL[(size_t)CC*CC];
__device__ __nv_bfloat16 g_fc1H[(size_t)MLPD*CC], g_fc1L[(size_t)MLPD*CC];
__device__ __nv_bfloat16 g_fc2H[(size_t)MLPD*CC], g_fc2L[(size_t)MLPD*CC];

// ---------------------------------------------------------------------------
// Helpers
// ---------------------------------------------------------------------------
union Pack4 { __nv_bfloat16 h[4]; uint2 u; };

__device__ __forceinline__ uint32_t smem_u32(const void* p) {
    uint32_t a;
    asm("{ .reg .u64 t; cvta.to.shared.u64 t, %1; cvt.u32.u64 %0, t; }" : "=r"(a) : "l"(p));
    return a;
}

__device__ __forceinline__ void cpasync16(uint32_t dst, const void* src) {
    asm volatile("cp.async.cg.shared.global [%0], [%1], 16;" :: "r"(dst), "l"(src));
}
#define CP_COMMIT() asm volatile("cp.async.commit_group;" ::: "memory")
#define CP_WAIT(n)  asm volatile("cp.async.wait_group %0;" :: "n"(n) : "memory")

#define MMA_BF16(d, a, b0v, b1v)                                           \
    asm volatile("mma.sync.aligned.m16n8k16.row.col.f32.bf16.bf16.f32 "    \
        "{%0,%1,%2,%3}, {%4,%5,%6,%7}, {%8,%9}, {%0,%1,%2,%3};"            \
        : "+f"(d[0]), "+f"(d[1]), "+f"(d[2]), "+f"(d[3])                   \
        : "r"(a[0]), "r"(a[1]), "r"(a[2]), "r"(a[3]), "r"(b0v), "r"(b1v))

__device__ __forceinline__ void split_pack2(float x, float y,
                                            unsigned int& hi, unsigned int& lo) {
    __nv_bfloat16 xh = __float2bfloat16_rn(x);
    __nv_bfloat16 yh = __float2bfloat16_rn(y);
    __nv_bfloat16 xl = __float2bfloat16_rn(x - __bfloat162float(xh));
    __nv_bfloat16 yl = __float2bfloat16_rn(y - __bfloat162float(yh));
    hi = (unsigned int)__bfloat16_as_ushort(xh) |
         ((unsigned int)__bfloat16_as_ushort(yh) << 16);
    lo = (unsigned int)__bfloat16_as_ushort(xl) |
         ((unsigned int)__bfloat16_as_ushort(yl) << 16);
}

// ---------------------------------------------------------------------------
// Elementwise fp32 -> (hi, lo) bf16 split
// ---------------------------------------------------------------------------
__global__ void split_fp32(const float* __restrict__ in,
                           __nv_bfloat16* __restrict__ H,
                           __nv_bfloat16* __restrict__ L, int n4) {
    int i = blockIdx.x * blockDim.x + threadIdx.x;
    if (i >= n4) return;
    float4 v = reinterpret_cast<const float4*>(in)[i];
    float f[4] = {v.x, v.y, v.z, v.w};
    Pack4 Hp, Lp;
    #pragma unroll
    for (int j = 0; j < 4; j++) {
        __nv_bfloat16 hv = __float2bfloat16_rn(f[j]);
        Hp.h[j] = hv;
        Lp.h[j] = __float2bfloat16_rn(f[j] - __bfloat162float(hv));
    }
    reinterpret_cast<uint2*>(H)[i] = Hp.u;
    reinterpret_cast<uint2*>(L)[i] = Lp.u;
}

// ---------------------------------------------------------------------------
// RMSNorm with split epilogue
// ---------------------------------------------------------------------------
__global__ void rmsnorm_split_kernel(const float* __restrict__ x,
                                     __nv_bfloat16* __restrict__ H,
                                     __nv_bfloat16* __restrict__ L) {
    int row = blockIdx.x;
    const float* xr = x + (size_t)row * CC;
    float ss = 0.f;
    for (int c = threadIdx.x; c < CC; c += blockDim.x) {
        float vv = xr[c];
        ss += vv * vv;
    }
    __shared__ float red[32];
    #pragma unroll
    for (int off = 16; off; off >>= 1) ss += __shfl_xor_sync(0xffffffffu, ss, off);
    int wid = threadIdx.x >> 5, lane = threadIdx.x & 31;
    if (lane == 0) red[wid] = ss;
    __syncthreads();
    if (wid == 0) {
        float v2 = lane < (blockDim.x >> 5) ? red[lane] : 0.f;
        #pragma unroll
        for (int off = 16; off; off >>= 1) v2 += __shfl_xor_sync(0xffffffffu, v2, off);
        if (lane == 0) red[0] = rsqrtf(v2 / (float)CC + EPS);
    }
    __syncthreads();
    float r = red[0];
    size_t base = (size_t)row * CC;
    for (int c = threadIdx.x * 2; c < CC; c += blockDim.x * 2) {
        float a = xr[c] * r, b = xr[c + 1] * r;
        unsigned int hi, lo;
        split_pack2(a, b, hi, lo);
        *reinterpret_cast<unsigned int*>(&H[base + c]) = hi;
        *reinterpret_cast<unsigned int*>(&L[base + c]) = lo;
    }
}

// ---------------------------------------------------------------------------
// bf16x3 GEMM, pre-split operands, cp.async 2-stage pipeline, 2 CTAs/SM.
// Block 128x128x32, 256 threads = 8 warps, warp tile 32x64 (grid 4m x 2n).
// ---------------------------------------------------------------------------
enum { EPI_F32 = 0, EPI_ADDF = 1, EPI_RELU2S = 2 };

#define GP_PART   10240              // bytes per part (128 rows x 80B pitch)
#define GP_STAGE  (4*GP_PART)        // AH,AL,BH,BL
#define GP_NSTG   2
#define GP_SMEM   (GP_NSTG*GP_STAGE) // 81920 bytes -> 2 CTAs/SM

__device__ __forceinline__ void gp_issue(
    uint32_t sb32, int buf, int tid,
    const __nv_bfloat16* __restrict__ AH, const __nv_bfloat16* __restrict__ AL,
    const __nv_bfloat16* __restrict__ BH, const __nv_bfloat16* __restrict__ BL,
    int bm, int bn, int K, int k0)
{
    int row = tid >> 1;               // 0..127
    int half = tid & 1;               // 0..1 -> 32B halves
    size_t offA = (size_t)(bm + row) * K + k0 + half * 16;
    size_t offB = (size_t)(bn + row) * K + k0 + half * 16;
    uint32_t d = sb32 + buf * GP_STAGE + row * 80 + half * 32;
    cpasync16(d,                    AH + offA);
    cpasync16(d + 16,               AH + offA + 8);
    cpasync16(d + GP_PART,          AL + offA);
    cpasync16(d + GP_PART + 16,     AL + offA + 8);
    cpasync16(d + 2 * GP_PART,      BH + offB);
    cpasync16(d + 2 * GP_PART + 16, BH + offB + 8);
    cpasync16(d + 3 * GP_PART,      BL + offB);
    cpasync16(d + 3 * GP_PART + 16, BL + offB + 8);
}

template <int EPI>
__global__ __launch_bounds__(256, 2) void gemm_pre(
    const __nv_bfloat16* __restrict__ AH, const __nv_bfloat16* __restrict__ AL,
    const __nv_bfloat16* __restrict__ BH, const __nv_bfloat16* __restrict__ BL,
    const float* __restrict__ Res, float* __restrict__ C,
    __nv_bfloat16* __restrict__ CH, __nv_bfloat16* __restrict__ CL,
    int M, int N, int K)
{
    extern __shared__ char smp[];
    uint32_t sb32 = smem_u32(smp);
    int tid = threadIdx.x;
    int bm = blockIdx.y * 128;
    int bn = blockIdx.x * 128;
    int wid = tid >> 5, lane = tid & 31;
    int wm = (wid & 3) * 32;          // warp m offset (4 warps down)
    int wn = (wid >> 2) * 64;         // warp n offset (2 warps across)
    int lt = lane >> 2, g = lane & 3;

    float acc[2][8][4];
    #pragma unroll
    for (int i = 0; i < 2; i++)
        #pragma unroll
        for (int j = 0; j < 8; j++)
            #pragma unroll
            for (int r = 0; r < 4; r++) acc[i][j][r] = 0.f;

    int nst = K / 32;
    gp_issue(sb32, 0, tid, AH, AL, BH, BL, bm, bn, K, 0);
    CP_COMMIT();

    for (int it = 0; it < nst; it++) {
        if (it + 1 < nst) {
            gp_issue(sb32, (it + 1) & 1, tid, AH, AL, BH, BL, bm, bn, K, (it + 1) * 32);
            CP_COMMIT();
            CP_WAIT(1);
        } else {
            CP_WAIT(0);
        }
        __syncthreads();

        const unsigned int* base =
            reinterpret_cast<const unsigned int*>(smp + (it & 1) * GP_STAGE);
        const unsigned int* AHw = base;
        const unsigned int* ALw = base + 2560;
        const unsigned int* BHw = base + 5120;
        const unsigned int* BLw = base + 7680;

        #pragma unroll
        for (int kk2 = 0; kk2 < 2; kk2++) {
            int kw = kk2 * 8;
            unsigned int ah[2][4], al[2][4];
            #pragma unroll
            for (int mi = 0; mi < 2; mi++) {
                int m0 = wm + mi * 16 + lt;
                int base0 = m0 * 20 + kw + g;
                int base1 = base0 + 160;          // +8 rows
                ah[mi][0] = AHw[base0];
                ah[mi][1] = AHw[base1];
                ah[mi][2] = AHw[base0 + 4];
                ah[mi][3] = AHw[base1 + 4];
                al[mi][0] = ALw[base0];
                al[mi][1] = ALw[base1];
                al[mi][2] = ALw[base0 + 4];
                al[mi][3] = ALw[base1 + 4];
            }
            #pragma unroll
            for (int ni = 0; ni < 8; ni++) {
                int n0 = wn + ni * 8 + lt;
                int nb = n0 * 20 + kw + g;
                unsigned int bh0 = BHw[nb], bh1 = BHw[nb + 4];
                unsigned int bl0 = BLw[nb], bl1 = BLw[nb + 4];
                #pragma unroll
                for (int mi = 0; mi < 2; mi++) {
                    MMA_BF16(acc[mi][ni], ah[mi], bh0, bh1);
                    MMA_BF16(acc[mi][ni], ah[mi], bl0, bl1);
                    MMA_BF16(acc[mi][ni], al[mi], bh0, bh1);
                }
            }
        }
        __syncthreads();
    }

    // epilogue
    #pragma unroll
    for (int mi = 0; mi < 2; mi++) {
        #pragma unroll
        for (int ni = 0; ni < 8; ni++) {
            int r0 = bm + wm + mi * 16 + lt;
            int c0 = bn + wn + ni * 8 + g * 2;
            float2 v0 = {acc[mi][ni][0], acc[mi][ni][1]};
            float2 v1 = {acc[mi][ni][2], acc[mi][ni][3]};
            if (EPI == EPI_RELU2S) {
                v0.x = fmaxf(v0.x, 0.f); v0.x *= v0.x;
                v0.y = fmaxf(v0.y, 0.f); v0.y *= v0.y;
                v1.x = fmaxf(v1.x, 0.f); v1.x *= v1.x;
                v1.y = fmaxf(v1.y, 0.f); v1.y *= v1.y;
                unsigned int h0, l0, h1, l1;
                split_pack2(v0.x, v0.y, h0, l0);
                split_pack2(v1.x, v1.y, h1, l1);
                *reinterpret_cast<unsigned int*>(&CH[(size_t)r0 * N + c0]) = h0;
                *reinterpret_cast<unsigned int*>(&CL[(size_t)r0 * N + c0]) = l0;
                *reinterpret_cast<unsigned int*>(&CH[(size_t)(r0 + 8) * N + c0]) = h1;
                *reinterpret_cast<unsigned int*>(&CL[(size_t)(r0 + 8) * N + c0]) = l1;
            } else {
                if (EPI == EPI_ADDF) {
                    float2 r0v = *reinterpret_cast<const float2*>(&Res[(size_t)r0 * N + c0]);
                    float2 r1v = *reinterpret_cast<const float2*>(&Res[(size_t)(r0 + 8) * N + c0]);
                    v0.x += r0v.x; v0.y += r0v.y;
                    v1.x += r1v.x; v1.y += r1v.y;
                }
                *reinterpret_cast<float2*>(&C[(size_t)r0 * N + c0]) = v0;
                *reinterpret_cast<float2*>(&C[(size_t)(r0 + 8) * N + c0]) = v1;
            }
        }
    }
}

// ---------------------------------------------------------------------------
// bf16x3 flash attention via mma.sync (proven R9/R10 version)
// ---------------------------------------------------------------------------
#define AQH 0
#define AQL 8704
#define AKH 17408
#define AKL 26112
#define AVH 34816
#define AVL 44032
#define ATT_SMEM 106496   // bytes
#define WQH 0
#define WQL 4352
#define WKH 8704
#define WKL 13056
#define WVH 17408
#define WVL 22016

__global__ __launch_bounds__(128) void attn_mma(
    const float* __restrict__ q, const float* __restrict__ k,
    const float* __restrict__ v,
    __nv_bfloat16* __restrict__ oH, __nv_bfloat16* __restrict__ oL)
{
    extern __shared__ char attsm[];
    __nv_bfloat16* sb = reinterpret_cast<__nv_bfloat16*>(attsm);
    unsigned int* s32 = reinterpret_cast<unsigned int*>(attsm);

    int tid = threadIdx.x;
    int wid = tid >> 5, lane = tid & 31;
    int lt = lane >> 2, g = lane & 3;
    int wrow = wid * 16;
    int qt = blockIdx.x, h = blockIdx.y, b = blockIdx.z;
    int qb = qt * 64;
    const float scale = 0.08838834764831845f;  // 1/sqrt(128)
    size_t base = ((size_t)b * TT) * CC + (size_t)h * HD;

    #pragma unroll
    for (int i = 0; i < 16; i++) {
        int lin = tid + i * 128;
        int r = lin >> 5, c4 = (lin & 31) * 4;
        float4 vq = *reinterpret_cast<const float4*>(&q[base + (size_t)(qb + r) * CC + c4]);
        float f[4] = {vq.x * scale, vq.y * scale, vq.z * scale, vq.w * scale};
        Pack4 H, L;
        #pragma unroll
        for (int j = 0; j < 4; j++) {
            __nv_bfloat16 hv = __float2bfloat16_rn(f[j]);
            H.h[j] = hv;
            L.h[j] = __float2bfloat16_rn(f[j] - __bfloat162float(hv));
        }
        *reinterpret_cast<uint2*>(&sb[AQH + r * 136 + c4]) = H.u;
        *reinterpret_cast<uint2*>(&sb[AQL + r * 136 + c4]) = L.u;
    }

    float oacc[16][4];
    #pragma unroll
    for (int i = 0; i < 16; i++)
        #pragma unroll
        for (int j = 0; j < 4; j++) oacc[i][j] = 0.f;
    float m0 = -1e30f, m1 = -1e30f, l0 = 0.f, l1 = 0.f;

    for (int nt = 0; nt <= qt; nt++) {
        int kb = nt * 64;
        #pragma unroll
        for (int i = 0; i < 16; i++) {
            int lin = tid + i * 128;
            int r = lin >> 5, c4 = (lin & 31) * 4;
            float4 vk = *reinterpret_cast<const float4*>(&k[base + (size_t)(kb + r) * CC + c4]);
            float f[4] = {vk.x, vk.y, vk.z, vk.w};
            Pack4 H, L;
            #pragma unroll
            for (int j = 0; j < 4; j++) {
                __nv_bfloat16 hv = __float2bfloat16_rn(f[j]);
                H.h[j] = hv;
                L.h[j] = __float2bfloat16_rn(f[j] - __bfloat162float(hv));
            }
            *reinterpret_cast<uint2*>(&sb[AKH + r * 136 + c4]) = H.u;
            *reinterpret_cast<uint2*>(&sb[AKL + r * 136 + c4]) = L.u;
        }
        #pragma unroll
        for (int i = 0; i < 16; i++) {
            int lin = tid + i * 128;
            int r = lin & 63;
            int c4 = ((lin >> 6) & 31) * 4;
            float4 vv = *reinterpret_cast<const float4*>(&v[base + (size_t)(kb + r) * CC + c4]);
            float f[4] = {vv.x, vv.y, vv.z, vv.w};
            #pragma unroll
            for (int j = 0; j < 4; j++) {
                __nv_bfloat16 hv = __float2bfloat16_rn(f[j]);
                sb[AVH + (c4 + j) * 72 + r] = hv;
                sb[AVL + (c4 + j) * 72 + r] = __float2bfloat16_rn(f[j] - __bfloat162float(hv));
            }
        }
        __syncthreads();

        float sacc[8][4];
        #pragma unroll
        for (int i = 0; i < 8; i++)
            #pragma unroll
            for (int j = 0; j < 4; j++) sacc[i][j] = 0.f;

        #pragma unroll
        for (int ks = 0; ks < 8; ks++) {
            unsigned int aH[4], aL[4];
            int ab = (wrow + lt) * 68 + ks * 8 + g;
            aH[0] = s32[WQH + ab];       aH[1] = s32[WQH + ab + 544];
            aH[2] = s32[WQH + ab + 4];   aH[3] = s32[WQH + ab + 548];
            aL[0] = s32[WQL + ab];       aL[1] = s32[WQL + ab + 544];
            aL[2] = s32[WQL + ab + 4];   aL[3] = s32[WQL + ab + 548];
            #pragma unroll
            for (int ni = 0; ni < 8; ni++) {
                int bb = (ni * 8 + lt) * 68 + ks * 8 + g;
                unsigned int bh0 = s32[WKH + bb], bh1 = s32[WKH + bb + 4];
                unsigned int bl0 = s32[WKL + bb], bl1 = s32[WKL + bb + 4];
                MMA_BF16(sacc[ni], aH, bh0, bh1);
                MMA_BF16(sacc[ni], aH, bl0, bl1);
                MMA_BF16(sacc[ni], aL, bh0, bh1);
            }
        }

        if (nt == qt) {
            int row0 = qb + wrow + lt, row1 = row0 + 8;
            #pragma unroll
            for (int ni = 0; ni < 8; ni++) {
                int c0 = kb + ni * 8 + 2 * g;
                if (c0 > row0)     sacc[ni][0] = -1e30f;
                if (c0 + 1 > row0) sacc[ni][1] = -1e30f;
                if (c0 > row1)     sacc[ni][2] = -1e30f;
                if (c0 + 1 > row1) sacc[ni][3] = -1e30f;
            }
        }

        float rm0 = -1e30f, rm1 = -1e30f;
        #pragma unroll
        for (int ni = 0; ni < 8; ni++) {
            rm0 = fmaxf(rm0, fmaxf(sacc[ni][0], sacc[ni][1]));
            rm1 = fmaxf(rm1, fmaxf(sacc[ni][2], sacc[ni][3]));
        }
        rm0 = fmaxf(rm0, __shfl_xor_sync(0xffffffffu, rm0, 1));
        rm0 = fmaxf(rm0, __shfl_xor_sync(0xffffffffu, rm0, 2));
        rm1 = fmaxf(rm1, __shfl_xor_sync(0xffffffffu, rm1, 1));
        rm1 = fmaxf(rm1, __shfl_xor_sync(0xffffffffu, rm1, 2));
        float mn0 = fmaxf(m0, rm0), mn1 = fmaxf(m1, rm1);
        float al0 = __expf(m0 - mn0), al1 = __expf(m1 - mn1);
        m0 = mn0; m1 = mn1;
        float rs0 = 0.f, rs1 = 0.f;
        #pragma unroll
        for (int ni = 0; ni < 8; ni++) {
            sacc[ni][0] = __expf(sacc[ni][0] - m0);
            sacc[ni][1] = __expf(sacc[ni][1] - m0);
            sacc[ni][2] = __expf(sacc[ni][2] - m1);
            sacc[ni][3] = __expf(sacc[ni][3] - m1);
            rs0 += sacc[ni][0] + sacc[ni][1];
            rs1 += sacc[ni][2] + sacc[ni][3];
        }
        l0 = l0 * al0 + rs0;
        l1 = l1 * al1 + rs1;
        #pragma unroll
        for (int ni = 0; ni < 16; ni++) {
            oacc[ni][0] *= al0; oacc[ni][1] *= al0;
            oacc[ni][2] *= al1; oacc[ni][3] *= al1;
        }

        #pragma unroll
        for (int kk = 0; kk < 4; kk++) {
            unsigned int pH[4], pL[4];
            split_pack2(sacc[2 * kk][0],     sacc[2 * kk][1],     pH[0], pL[0]);
            split_pack2(sacc[2 * kk][2],     sacc[2 * kk][3],     pH[1], pL[1]);
            split_pack2(sacc[2 * kk + 1][0], sacc[2 * kk + 1][1], pH[2], pL[2]);
            split_pack2(sacc[2 * kk + 1][2], sacc[2 * kk + 1][3], pH[3], pL[3]);
            #pragma unroll
            for (int ni = 0; ni < 16; ni++) {
                int vb2 = (ni * 8 + lt) * 36 + kk * 8 + g;
                unsigned int vh0 = s32[WVH + vb2], vh1 = s32[WVH + vb2 + 4];
                unsigned int vl0 = s32[WVL + vb2], vl1 = s32[WVL + vb2 + 4];
                MMA_BF16(oacc[ni], pH, vh0, vh1);
                MMA_BF16(oacc[ni], pH, vl0, vl1);
                MMA_BF16(oacc[ni], pL, vh0, vh1);
            }
        }
        __syncthreads();
    }

    l0 += __shfl_xor_sync(0xffffffffu, l0, 1);
    l0 += __shfl_xor_sync(0xffffffffu, l0, 2);
    l1 += __shfl_xor_sync(0xffffffffu, l1, 1);
    l1 += __shfl_xor_sync(0xffffffffu, l1, 2);
    float inv0 = 1.f / l0, inv1 = 1.f / l1;
    int row0 = qb + wrow + lt;
    #pragma unroll
    for (int ni = 0; ni < 16; ni++) {
        size_t o0 = base + (size_t)row0 * CC + ni * 8 + 2 * g;
        size_t o1 = o0 + (size_t)8 * CC;
        unsigned int h0, l0u, h1, l1u;
        split_pack2(oacc[ni][0] * inv0, oacc[ni][1] * inv0, h0, l0u);
        split_pack2(oacc[ni][2] * inv1, oacc[ni][3] * inv1, h1, l1u);
        *reinterpret_cast<unsigned int*>(&oH[o0]) = h0;
        *reinterpret_cast<unsigned int*>(&oL[o0]) = l0u;
        *reinterpret_cast<unsigned int*>(&oH[o1]) = h1;
        *reinterpret_cast<unsigned int*>(&oL[o1]) = l1u;
    }
}

// ---------------------------------------------------------------------------
// Launch
// ---------------------------------------------------------------------------
extern "C" void kernel_launch(void* const* d_in, const int* in_sizes, int n_in,
                              void* d_out, int out_size) {
    const float* x   = (const float*)d_in[0];
    const float* wq  = (const float*)d_in[1];
    const float* wk  = (const float*)d_in[2];
    const float* wv  = (const float*)d_in[3];
    const float* wo  = (const float*)d_in[4];
    const float* fc1 = (const float*)d_in[5];
    const float* fc2 = (const float*)d_in[6];
    float* out = (float*)d_out;

    float *q, *k, *v, *x1;
    cudaGetSymbolAddress((void**)&q,  g_q);
    cudaGetSymbolAddress((void**)&k,  g_k);
    cudaGetSymbolAddress((void**)&v,  g_v);
    cudaGetSymbolAddress((void**)&x1, g_x1);

    __nv_bfloat16 *hH, *hL, *attH, *attL, *mH, *mL;
    __nv_bfloat16 *wqH, *wqL, *wkH, *wkL, *wvH, *wvL, *woH, *woL;
    __nv_bfloat16 *fc1H, *fc1L, *fc2H, *fc2L;
    cudaGetSymbolAddress((void**)&hH, g_hH);     cudaGetSymbolAddress((void**)&hL, g_hL);
    cudaGetSymbolAddress((void**)&attH, g_attH); cudaGetSymbolAddress((void**)&attL, g_attL);
    cudaGetSymbolAddress((void**)&mH, g_mH);     cudaGetSymbolAddress((void**)&mL, g_mL);
    cudaGetSymbolAddress((void**)&wqH, g_wqH);   cudaGetSymbolAddress((void**)&wqL, g_wqL);
    cudaGetSymbolAddress((void**)&wkH, g_wkH);   cudaGetSymbolAddress((void**)&wkL, g_wkL);
    cudaGetSymbolAddress((void**)&wvH, g_wvH);   cudaGetSymbolAddress((void**)&wvL, g_wvL);
    cudaGetSymbolAddress((void**)&woH, g_woH);   cudaGetSymbolAddress((void**)&woL, g_woL);
    cudaGetSymbolAddress((void**)&fc1H, g_fc1H); cudaGetSymbolAddress((void**)&fc1L, g_fc1L);
    cudaGetSymbolAddress((void**)&fc2H, g_fc2H); cudaGetSymbolAddress((void**)&fc2L, g_fc2L);

    cudaFuncSetAttribute(attn_mma, cudaFuncAttributeMaxDynamicSharedMemorySize, ATT_SMEM);
    cudaFuncSetAttribute(gemm_pre<EPI_F32>,    cudaFuncAttributeMaxDynamicSharedMemorySize, GP_SMEM);
    cudaFuncSetAttribute(gemm_pre<EPI_ADDF>,   cudaFuncAttributeMaxDynamicSharedMemorySize, GP_SMEM);
    cudaFuncSetAttribute(gemm_pre<EPI_RELU2S>, cudaFuncAttributeMaxDynamicSharedMemorySize, GP_SMEM);

    // 0) split weights
    {
        int n4w = CC * CC / 4;
        int n4f = MLPD * CC / 4;
        split_fp32<<<(n4w + 255) / 256, 256>>>(wq, wqH, wqL, n4w);
        split_fp32<<<(n4w + 255) / 256, 256>>>(wk, wkH, wkL, n4w);
        split_fp32<<<(n4w + 255) / 256, 256>>>(wv, wvH, wvL, n4w);
        split_fp32<<<(n4f + 255) / 256, 256>>>(fc1, fc1H, fc1L, n4f);
        split_fp32<<<(n4f + 255) / 256, 256>>>(fc2, fc2H, fc2L, n4f);
        split_fp32<<<(n4w + 255) / 256, 256>>>(wo, woH, woL, n4w);
    }

    // 1) h = rmsnorm(x)  (split)
    rmsnorm_split_kernel<<<BT, 256>>>(x, hH, hL);

    // 2-4) q,k,v = h @ w^T  (fp32 out for attention)
    dim3 thr(256);
    dim3 g_qkv(CC / 128, BT / 128);
    gemm_pre<EPI_F32><<<g_qkv, thr, GP_SMEM>>>(hH, hL, wqH, wqL, nullptr, q, nullptr, nullptr, BT, CC, CC);
    gemm_pre<EPI_F32><<<g_qkv, thr, GP_SMEM>>>(hH, hL, wkH, wkL, nullptr, k, nullptr, nullptr, BT, CC, CC);
    gemm_pre<EPI_F32><<<g_qkv, thr, GP_SMEM>>>(hH, hL, wvH, wvL, nullptr, v, nullptr, nullptr, BT, CC, CC);

    // 5) causal attention -> split att
    dim3 g_att_grid(TT / 64, HH, BB);
    attn_mma<<<g_att_grid, 128, ATT_SMEM>>>(q, k, v, attH, attL);

    // 6) x1 = x + att @ wo^T
    gemm_pre<EPI_ADDF><<<g_qkv, thr, GP_SMEM>>>(attH, attL, woH, woL, x, x1, nullptr, nullptr, BT, CC, CC);

    // 7) h = rmsnorm(x1)  (split)
    rmsnorm_split_kernel<<<BT, 256>>>(x1, hH, hL);

    // 8) m = relu(h @ fc1^T)^2  (split out)
    dim3 g_fc1(MLPD / 128, BT / 128);
    gemm_pre<EPI_RELU2S><<<g_fc1, thr, GP_SMEM>>>(hH, hL, fc1H, fc1L, nullptr, nullptr, mH, mL, BT, MLPD, CC);

    // 9) out = x1 + m @ fc2^T
    dim3 g_fc2(CC / 128, BT / 128);
    gemm_pre<EPI_ADDF><<<g_fc2, thr, GP_SMEM>>>(mH, mL, fc2H, fc2L, x1, out, nullptr, nullptr, BT, CC, MLPD);
}

// round 16
// speedup vs baseline: 1.7572x; 1.4117x over previous
#include <cuda_runtime.h>
#include <cuda_bf16.h>
#include <cuda_fp16.h>
#include <cstdint>
#include <stdint.h>
#include <math.h>

// Problem constants
#define BB 2
#define TT 2048
#define CC 2048
#define HH 16
#define HD 128
#define MLPD 8192
#define BT (BB*TT)          // 4096 rows
#define EPS 1e-5f

// ---------------------------------------------------------------------------
// Scratch (device globals; no allocations allowed)
// ---------------------------------------------------------------------------
__device__ float g_q[(size_t)BT*CC];
__device__ float g_k[(size_t)BT*CC];
__device__ float g_v[(size_t)BT*CC];
__device__ float g_x1[(size_t)BT*CC];

// fp16 split activations (hi/lo) and fp16 weights (hi only)
__device__ __half g_hH[(size_t)BT*CC],   g_hL[(size_t)BT*CC];
__device__ __half g_attH[(size_t)BT*CC], g_attL[(size_t)BT*CC];
__device__ __half g_mH[(size_t)BT*MLPD], g_mL[(size_t)BT*MLPD];
__device__ __half g_wq16[(size_t)CC*CC];
__device__ __half g_wk16[(size_t)CC*CC];
__device__ __half g_wv16[(size_t)CC*CC];
__device__ __half g_wo16[(size_t)CC*CC];
__device__ __half g_fc1_16[(size_t)MLPD*CC];
__device__ __half g_fc2_16[(size_t)MLPD*CC];

// ---------------------------------------------------------------------------
// Helpers
// ---------------------------------------------------------------------------
union Pack4 { __nv_bfloat16 h[4]; uint2 u; };
union PackH4 { __half h[4]; uint2 u; };

__device__ __forceinline__ uint32_t smem_u32(const void* p) {
    uint32_t a;
    asm("{ .reg .u64 t; cvta.to.shared.u64 t, %1; cvt.u32.u64 %0, t; }" : "=r"(a) : "l"(p));
    return a;
}

__device__ __forceinline__ void cpasync16(uint32_t dst, const void* src) {
    asm volatile("cp.async.cg.shared.global [%0], [%1], 16;" :: "r"(dst), "l"(src));
}
#define CP_COMMIT() asm volatile("cp.async.commit_group;" ::: "memory")
#define CP_WAIT(n)  asm volatile("cp.async.wait_group %0;" :: "n"(n) : "memory")

#define MMA_BF16(d, a, b0v, b1v)                                           \
    asm volatile("mma.sync.aligned.m16n8k16.row.col.f32.bf16.bf16.f32 "    \
        "{%0,%1,%2,%3}, {%4,%5,%6,%7}, {%8,%9}, {%0,%1,%2,%3};"            \
        : "+f"(d[0]), "+f"(d[1]), "+f"(d[2]), "+f"(d[3])                   \
        : "r"(a[0]), "r"(a[1]), "r"(a[2]), "r"(a[3]), "r"(b0v), "r"(b1v))

#define MMA_FP16(d, a, b0v, b1v)                                           \
    asm volatile("mma.sync.aligned.m16n8k16.row.col.f32.f16.f16.f32 "      \
        "{%0,%1,%2,%3}, {%4,%5,%6,%7}, {%8,%9}, {%0,%1,%2,%3};"            \
        : "+f"(d[0]), "+f"(d[1]), "+f"(d[2]), "+f"(d[3])                   \
        : "r"(a[0]), "r"(a[1]), "r"(a[2]), "r"(a[3]), "r"(b0v), "r"(b1v))

// bf16 hi/lo pack (attention internals)
__device__ __forceinline__ void split_pack2(float x, float y,
                                            unsigned int& hi, unsigned int& lo) {
    __nv_bfloat16 xh = __float2bfloat16_rn(x);
    __nv_bfloat16 yh = __float2bfloat16_rn(y);
    __nv_bfloat16 xl = __float2bfloat16_rn(x - __bfloat162float(xh));
    __nv_bfloat16 yl = __float2bfloat16_rn(y - __bfloat162float(yh));
    hi = (unsigned int)__bfloat16_as_ushort(xh) |
         ((unsigned int)__bfloat16_as_ushort(yh) << 16);
    lo = (unsigned int)__bfloat16_as_ushort(xl) |
         ((unsigned int)__bfloat16_as_ushort(yl) << 16);
}

// fp16 hi/lo pack (GEMM activations)
__device__ __forceinline__ void split_pack2h(float x, float y,
                                             unsigned int& hi, unsigned int& lo) {
    __half xh = __float2half_rn(x);
    __half yh = __float2half_rn(y);
    __half xl = __float2half_rn(x - __half2float(xh));
    __half yl = __float2half_rn(y - __half2float(yh));
    hi = (unsigned int)__half_as_ushort(xh) |
         ((unsigned int)__half_as_ushort(yh) << 16);
    lo = (unsigned int)__half_as_ushort(xl) |
         ((unsigned int)__half_as_ushort(yl) << 16);
}

// ---------------------------------------------------------------------------
// Weight conversion fp32 -> fp16
// ---------------------------------------------------------------------------
__global__ void conv_fp16(const float* __restrict__ in,
                          __half* __restrict__ H, int n4) {
    int i = blockIdx.x * blockDim.x + threadIdx.x;
    if (i >= n4) return;
    float4 v = reinterpret_cast<const float4*>(in)[i];
    PackH4 Hp;
    Hp.h[0] = __float2half_rn(v.x);
    Hp.h[1] = __float2half_rn(v.y);
    Hp.h[2] = __float2half_rn(v.z);
    Hp.h[3] = __float2half_rn(v.w);
    reinterpret_cast<uint2*>(H)[i] = Hp.u;
}

// ---------------------------------------------------------------------------
// RMSNorm with fp16 split epilogue
// ---------------------------------------------------------------------------
__global__ void rmsnorm_split_kernel(const float* __restrict__ x,
                                     __half* __restrict__ H,
                                     __half* __restrict__ L) {
    int row = blockIdx.x;
    const float* xr = x + (size_t)row * CC;
    float ss = 0.f;
    for (int c = threadIdx.x; c < CC; c += blockDim.x) {
        float vv = xr[c];
        ss += vv * vv;
    }
    __shared__ float red[32];
    #pragma unroll
    for (int off = 16; off; off >>= 1) ss += __shfl_xor_sync(0xffffffffu, ss, off);
    int wid = threadIdx.x >> 5, lane = threadIdx.x & 31;
    if (lane == 0) red[wid] = ss;
    __syncthreads();
    if (wid == 0) {
        float v2 = lane < (blockDim.x >> 5) ? red[lane] : 0.f;
        #pragma unroll
        for (int off = 16; off; off >>= 1) v2 += __shfl_xor_sync(0xffffffffu, v2, off);
        if (lane == 0) red[0] = rsqrtf(v2 / (float)CC + EPS);
    }
    __syncthreads();
    float r = red[0];
    size_t base = (size_t)row * CC;
    for (int c = threadIdx.x * 2; c < CC; c += blockDim.x * 2) {
        float a = xr[c] * r, b = xr[c + 1] * r;
        unsigned int hi, lo;
        split_pack2h(a, b, hi, lo);
        *reinterpret_cast<unsigned int*>(&H[base + c]) = hi;
        *reinterpret_cast<unsigned int*>(&L[base + c]) = lo;
    }
}

// ---------------------------------------------------------------------------
// fp16x2 GEMM: C = (AH+AL)[M,K] @ W[N,K]^T, cp.async 3-stage pipeline.
// Block 128x128x32, 512 threads, warp tile 32x32 (R10 proven structure).
// 2 MMAs per k16 step: aH*w + aL*w.
// ---------------------------------------------------------------------------
enum { EPI_F32 = 0, EPI_ADDF = 1, EPI_RELU2S = 2 };

#define GP_PART   10240              // bytes per part (128 rows x 80B pitch)
#define GP_STAGE  (3*GP_PART)        // AH, AL, W
#define GP_NSTG   3
#define GP_SMEM   (GP_NSTG*GP_STAGE) // 92160 bytes

__device__ __forceinline__ void gp_issue(
    uint32_t sb32, int buf, int tid,
    const __half* __restrict__ AH, const __half* __restrict__ AL,
    const __half* __restrict__ W,
    int bm, int bn, int K, int k0)
{
    int row = tid >> 2, c = tid & 3;
    size_t offA = (size_t)(bm + row) * K + k0 + c * 8;
    size_t offB = (size_t)(bn + row) * K + k0 + c * 8;
    uint32_t d = sb32 + buf * GP_STAGE + row * 80 + c * 16;
    cpasync16(d,               AH + offA);
    cpasync16(d + GP_PART,     AL + offA);
    cpasync16(d + 2 * GP_PART, W + offB);
}

template <int EPI>
__global__ __launch_bounds__(512, 1) void gemm_pre(
    const __half* __restrict__ AH, const __half* __restrict__ AL,
    const __half* __restrict__ W,
    const float* __restrict__ Res, float* __restrict__ C,
    __half* __restrict__ CH, __half* __restrict__ CL,
    int M, int N, int K)
{
    extern __shared__ char smp[];
    uint32_t sb32 = smem_u32(smp);
    int tid = threadIdx.x;
    int bm = blockIdx.y * 128;
    int bn = blockIdx.x * 128;
    int wid = tid >> 5, lane = tid & 31;
    int wm = (wid & 3) * 32;
    int wn = (wid >> 2) * 32;
    int lt = lane >> 2, g = lane & 3;

    float acc[2][4][4];
    #pragma unroll
    for (int i = 0; i < 2; i++)
        #pragma unroll
        for (int j = 0; j < 4; j++)
            #pragma unroll
            for (int r = 0; r < 4; r++) acc[i][j][r] = 0.f;

    int nst = K / 32;
    #pragma unroll
    for (int p = 0; p < 2; p++) {
        gp_issue(sb32, p, tid, AH, AL, W, bm, bn, K, p * 32);
        CP_COMMIT();
    }

    for (int it = 0; it < nst; it++) {
        if (it + 1 < nst) { CP_WAIT(1); } else { CP_WAIT(0); }
        __syncthreads();

        int b = it - (it / 3) * 3;   // it % 3
        const unsigned int* base =
            reinterpret_cast<const unsigned int*>(smp + b * GP_STAGE);
        const unsigned int* AHw = base;
        const unsigned int* ALw = base + 2560;
        const unsigned int* Ww  = base + 5120;

        #pragma unroll
        for (int kk2 = 0; kk2 < 2; kk2++) {
            int kw = kk2 * 8;
            unsigned int ah[2][4], al[2][4];
            #pragma unroll
            for (int mi = 0; mi < 2; mi++) {
                int m0 = wm + mi * 16 + lt;
                int base0 = m0 * 20 + kw + g;
                int base1 = (m0 + 8) * 20 + kw + g;
                ah[mi][0] = AHw[base0];
                ah[mi][1] = AHw[base1];
                ah[mi][2] = AHw[base0 + 4];
                ah[mi][3] = AHw[base1 + 4];
                al[mi][0] = ALw[base0];
                al[mi][1] = ALw[base1];
                al[mi][2] = ALw[base0 + 4];
                al[mi][3] = ALw[base1 + 4];
            }
            #pragma unroll
            for (int ni = 0; ni < 4; ni++) {
                int n0 = wn + ni * 8 + lt;
                int nb = n0 * 20 + kw + g;
                unsigned int b0 = Ww[nb], b1 = Ww[nb + 4];
                #pragma unroll
                for (int mi = 0; mi < 2; mi++) {
                    MMA_FP16(acc[mi][ni], ah[mi], b0, b1);
                    MMA_FP16(acc[mi][ni], al[mi], b0, b1);
                }
            }
        }

        if (it + 2 < nst) {
            int nb3 = (it + 2) - ((it + 2) / 3) * 3;
            gp_issue(sb32, nb3, tid, AH, AL, W, bm, bn, K, (it + 2) * 32);
            CP_COMMIT();
        }
    }

    // epilogue
    #pragma unroll
    for (int mi = 0; mi < 2; mi++) {
        #pragma unroll
        for (int ni = 0; ni < 4; ni++) {
            int r0 = bm + wm + mi * 16 + lt;
            int c0 = bn + wn + ni * 8 + g * 2;
            float2 v0 = {acc[mi][ni][0], acc[mi][ni][1]};
            float2 v1 = {acc[mi][ni][2], acc[mi][ni][3]};
            if (EPI == EPI_RELU2S) {
                v0.x = fmaxf(v0.x, 0.f); v0.x *= v0.x;
                v0.y = fmaxf(v0.y, 0.f); v0.y *= v0.y;
                v1.x = fmaxf(v1.x, 0.f); v1.x *= v1.x;
                v1.y = fmaxf(v1.y, 0.f); v1.y *= v1.y;
                unsigned int h0, l0, h1, l1;
                split_pack2h(v0.x, v0.y, h0, l0);
                split_pack2h(v1.x, v1.y, h1, l1);
                *reinterpret_cast<unsigned int*>(&CH[(size_t)r0 * N + c0]) = h0;
                *reinterpret_cast<unsigned int*>(&CL[(size_t)r0 * N + c0]) = l0;
                *reinterpret_cast<unsigned int*>(&CH[(size_t)(r0 + 8) * N + c0]) = h1;
                *reinterpret_cast<unsigned int*>(&CL[(size_t)(r0 + 8) * N + c0]) = l1;
            } else {
                if (EPI == EPI_ADDF) {
                    float2 r0v = *reinterpret_cast<const float2*>(&Res[(size_t)r0 * N + c0]);
                    float2 r1v = *reinterpret_cast<const float2*>(&Res[(size_t)(r0 + 8) * N + c0]);
                    v0.x += r0v.x; v0.y += r0v.y;
                    v1.x += r1v.x; v1.y += r1v.y;
                }
                *reinterpret_cast<float2*>(&C[(size_t)r0 * N + c0]) = v0;
                *reinterpret_cast<float2*>(&C[(size_t)(r0 + 8) * N + c0]) = v1;
            }
        }
    }
}

// ---------------------------------------------------------------------------
// bf16x3 flash attention via mma.sync (proven R9/R10; fp16 split outputs)
// ---------------------------------------------------------------------------
#define AQH 0
#define AQL 8704
#define AKH 17408
#define AKL 26112
#define AVH 34816
#define AVL 44032
#define ATT_SMEM 106496   // bytes
#define WQHo 0
#define WQLo 4352
#define WKHo 8704
#define WKLo 13056
#define WVHo 17408
#define WVLo 22016

__global__ __launch_bounds__(128) void attn_mma(
    const float* __restrict__ q, const float* __restrict__ k,
    const float* __restrict__ v,
    __half* __restrict__ oH, __half* __restrict__ oL)
{
    extern __shared__ char attsm[];
    __nv_bfloat16* sb = reinterpret_cast<__nv_bfloat16*>(attsm);
    unsigned int* s32 = reinterpret_cast<unsigned int*>(attsm);

    int tid = threadIdx.x;
    int wid = tid >> 5, lane = tid & 31;
    int lt = lane >> 2, g = lane & 3;
    int wrow = wid * 16;
    int qt = blockIdx.x, h = blockIdx.y, b = blockIdx.z;
    int qb = qt * 64;
    const float scale = 0.08838834764831845f;  // 1/sqrt(128)
    size_t base = ((size_t)b * TT) * CC + (size_t)h * HD;

    #pragma unroll
    for (int i = 0; i < 16; i++) {
        int lin = tid + i * 128;
        int r = lin >> 5, c4 = (lin & 31) * 4;
        float4 vq = *reinterpret_cast<const float4*>(&q[base + (size_t)(qb + r) * CC + c4]);
        float f[4] = {vq.x * scale, vq.y * scale, vq.z * scale, vq.w * scale};
        Pack4 H, L;
        #pragma unroll
        for (int j = 0; j < 4; j++) {
            __nv_bfloat16 hv = __float2bfloat16_rn(f[j]);
            H.h[j] = hv;
            L.h[j] = __float2bfloat16_rn(f[j] - __bfloat162float(hv));
        }
        *reinterpret_cast<uint2*>(&sb[AQH + r * 136 + c4]) = H.u;
        *reinterpret_cast<uint2*>(&sb[AQL + r * 136 + c4]) = L.u;
    }

    float oacc[16][4];
    #pragma unroll
    for (int i = 0; i < 16; i++)
        #pragma unroll
        for (int j = 0; j < 4; j++) oacc[i][j] = 0.f;
    float m0 = -1e30f, m1 = -1e30f, l0 = 0.f, l1 = 0.f;

    for (int nt = 0; nt <= qt; nt++) {
        int kb = nt * 64;
        #pragma unroll
        for (int i = 0; i < 16; i++) {
            int lin = tid + i * 128;
            int r = lin >> 5, c4 = (lin & 31) * 4;
            float4 vk = *reinterpret_cast<const float4*>(&k[base + (size_t)(kb + r) * CC + c4]);
            float f[4] = {vk.x, vk.y, vk.z, vk.w};
            Pack4 H, L;
            #pragma unroll
            for (int j = 0; j < 4; j++) {
                __nv_bfloat16 hv = __float2bfloat16_rn(f[j]);
                H.h[j] = hv;
                L.h[j] = __float2bfloat16_rn(f[j] - __bfloat162float(hv));
            }
            *reinterpret_cast<uint2*>(&sb[AKH + r * 136 + c4]) = H.u;
            *reinterpret_cast<uint2*>(&sb[AKL + r * 136 + c4]) = L.u;
        }
        #pragma unroll
        for (int i = 0; i < 16; i++) {
            int lin = tid + i * 128;
            int r = lin & 63;
            int c4 = ((lin >> 6) & 31) * 4;
            float4 vv = *reinterpret_cast<const float4*>(&v[base + (size_t)(kb + r) * CC + c4]);
            float f[4] = {vv.x, vv.y, vv.z, vv.w};
            #pragma unroll
            for (int j = 0; j < 4; j++) {
                __nv_bfloat16 hv = __float2bfloat16_rn(f[j]);
                sb[AVH + (c4 + j) * 72 + r] = hv;
                sb[AVL + (c4 + j) * 72 + r] = __float2bfloat16_rn(f[j] - __bfloat162float(hv));
            }
        }
        __syncthreads();

        float sacc[8][4];
        #pragma unroll
        for (int i = 0; i < 8; i++)
            #pragma unroll
            for (int j = 0; j < 4; j++) sacc[i][j] = 0.f;

        #pragma unroll
        for (int ks = 0; ks < 8; ks++) {
            unsigned int aH[4], aL[4];
            int ab = (wrow + lt) * 68 + ks * 8 + g;
            aH[0] = s32[WQHo + ab];       aH[1] = s32[WQHo + ab + 544];
            aH[2] = s32[WQHo + ab + 4];   aH[3] = s32[WQHo + ab + 548];
            aL[0] = s32[WQLo + ab];       aL[1] = s32[WQLo + ab + 544];
            aL[2] = s32[WQLo + ab + 4];   aL[3] = s32[WQLo + ab + 548];
            #pragma unroll
            for (int ni = 0; ni < 8; ni++) {
                int bb = (ni * 8 + lt) * 68 + ks * 8 + g;
                unsigned int bh0 = s32[WKHo + bb], bh1 = s32[WKHo + bb + 4];
                unsigned int bl0 = s32[WKLo + bb], bl1 = s32[WKLo + bb + 4];
                MMA_BF16(sacc[ni], aH, bh0, bh1);
                MMA_BF16(sacc[ni], aH, bl0, bl1);
                MMA_BF16(sacc[ni], aL, bh0, bh1);
            }
        }

        if (nt == qt) {
            int row0 = qb + wrow + lt, row1 = row0 + 8;
            #pragma unroll
            for (int ni = 0; ni < 8; ni++) {
                int c0 = kb + ni * 8 + 2 * g;
                if (c0 > row0)     sacc[ni][0] = -1e30f;
                if (c0 + 1 > row0) sacc[ni][1] = -1e30f;
                if (c0 > row1)     sacc[ni][2] = -1e30f;
                if (c0 + 1 > row1) sacc[ni][3] = -1e30f;
            }
        }

        float rm0 = -1e30f, rm1 = -1e30f;
        #pragma unroll
        for (int ni = 0; ni < 8; ni++) {
            rm0 = fmaxf(rm0, fmaxf(sacc[ni][0], sacc[ni][1]));
            rm1 = fmaxf(rm1, fmaxf(sacc[ni][2], sacc[ni][3]));
        }
        rm0 = fmaxf(rm0, __shfl_xor_sync(0xffffffffu, rm0, 1));
        rm0 = fmaxf(rm0, __shfl_xor_sync(0xffffffffu, rm0, 2));
        rm1 = fmaxf(rm1, __shfl_xor_sync(0xffffffffu, rm1, 1));
        rm1 = fmaxf(rm1, __shfl_xor_sync(0xffffffffu, rm1, 2));
        float mn0 = fmaxf(m0, rm0), mn1 = fmaxf(m1, rm1);
        float al0 = __expf(m0 - mn0), al1 = __expf(m1 - mn1);
        m0 = mn0; m1 = mn1;
        float rs0 = 0.f, rs1 = 0.f;
        #pragma unroll
        for (int ni = 0; ni < 8; ni++) {
            sacc[ni][0] = __expf(sacc[ni][0] - m0);
            sacc[ni][1] = __expf(sacc[ni][1] - m0);
            sacc[ni][2] = __expf(sacc[ni][2] - m1);
            sacc[ni][3] = __expf(sacc[ni][3] - m1);
            rs0 += sacc[ni][0] + sacc[ni][1];
            rs1 += sacc[ni][2] + sacc[ni][3];
        }
        l0 = l0 * al0 + rs0;
        l1 = l1 * al1 + rs1;
        #pragma unroll
        for (int ni = 0; ni < 16; ni++) {
            oacc[ni][0] *= al0; oacc[ni][1] *= al0;
            oacc[ni][2] *= al1; oacc[ni][3] *= al1;
        }

        #pragma unroll
        for (int kk = 0; kk < 4; kk++) {
            unsigned int pH[4], pL[4];
            split_pack2(sacc[2 * kk][0],     sacc[2 * kk][1],     pH[0], pL[0]);
            split_pack2(sacc[2 * kk][2],     sacc[2 * kk][3],     pH[1], pL[1]);
            split_pack2(sacc[2 * kk + 1][0], sacc[2 * kk + 1][1], pH[2], pL[2]);
            split_pack2(sacc[2 * kk + 1][2], sacc[2 * kk + 1][3], pH[3], pL[3]);
            #pragma unroll
            for (int ni = 0; ni < 16; ni++) {
                int vb2 = (ni * 8 + lt) * 36 + kk * 8 + g;
                unsigned int vh0 = s32[WVHo + vb2], vh1 = s32[WVHo + vb2 + 4];
                unsigned int vl0 = s32[WVLo + vb2], vl1 = s32[WVLo + vb2 + 4];
                MMA_BF16(oacc[ni], pH, vh0, vh1);
                MMA_BF16(oacc[ni], pH, vl0, vl1);
                MMA_BF16(oacc[ni], pL, vh0, vh1);
            }
        }
        __syncthreads();
    }

    l0 += __shfl_xor_sync(0xffffffffu, l0, 1);
    l0 += __shfl_xor_sync(0xffffffffu, l0, 2);
    l1 += __shfl_xor_sync(0xffffffffu, l1, 1);
    l1 += __shfl_xor_sync(0xffffffffu, l1, 2);
    float inv0 = 1.f / l0, inv1 = 1.f / l1;
    int row0 = qb + wrow + lt;
    #pragma unroll
    for (int ni = 0; ni < 16; ni++) {
        size_t o0 = base + (size_t)row0 * CC + ni * 8 + 2 * g;
        size_t o1 = o0 + (size_t)8 * CC;
        unsigned int h0, l0u, h1, l1u;
        split_pack2h(oacc[ni][0] * inv0, oacc[ni][1] * inv0, h0, l0u);
        split_pack2h(oacc[ni][2] * inv1, oacc[ni][3] * inv1, h1, l1u);
        *reinterpret_cast<unsigned int*>(&oH[o0]) = h0;
        *reinterpret_cast<unsigned int*>(&oL[o0]) = l0u;
        *reinterpret_cast<unsigned int*>(&oH[o1]) = h1;
        *reinterpret_cast<unsigned int*>(&oL[o1]) = l1u;
    }
}

// ---------------------------------------------------------------------------
// Launch
// ---------------------------------------------------------------------------
extern "C" void kernel_launch(void* const* d_in, const int* in_sizes, int n_in,
                              void* d_out, int out_size) {
    const float* x   = (const float*)d_in[0];
    const float* wq  = (const float*)d_in[1];
    const float* wk  = (const float*)d_in[2];
    const float* wv  = (const float*)d_in[3];
    const float* wo  = (const float*)d_in[4];
    const float* fc1 = (const float*)d_in[5];
    const float* fc2 = (const float*)d_in[6];
    float* out = (float*)d_out;

    float *q, *k, *v, *x1;
    cudaGetSymbolAddress((void**)&q,  g_q);
    cudaGetSymbolAddress((void**)&k,  g_k);
    cudaGetSymbolAddress((void**)&v,  g_v);
    cudaGetSymbolAddress((void**)&x1, g_x1);

    __half *hH, *hL, *attH, *attL, *mH, *mL;
    __half *wq16, *wk16, *wv16, *wo16, *fc116, *fc216;
    cudaGetSymbolAddress((void**)&hH, g_hH);     cudaGetSymbolAddress((void**)&hL, g_hL);
    cudaGetSymbolAddress((void**)&attH, g_attH); cudaGetSymbolAddress((void**)&attL, g_attL);
    cudaGetSymbolAddress((void**)&mH, g_mH);     cudaGetSymbolAddress((void**)&mL, g_mL);
    cudaGetSymbolAddress((void**)&wq16, g_wq16);
    cudaGetSymbolAddress((void**)&wk16, g_wk16);
    cudaGetSymbolAddress((void**)&wv16, g_wv16);
    cudaGetSymbolAddress((void**)&wo16, g_wo16);
    cudaGetSymbolAddress((void**)&fc116, g_fc1_16);
    cudaGetSymbolAddress((void**)&fc216, g_fc2_16);

    cudaFuncSetAttribute(attn_mma, cudaFuncAttributeMaxDynamicSharedMemorySize, ATT_SMEM);
    cudaFuncSetAttribute(gemm_pre<EPI_F32>,    cudaFuncAttributeMaxDynamicSharedMemorySize, GP_SMEM);
    cudaFuncSetAttribute(gemm_pre<EPI_ADDF>,   cudaFuncAttributeMaxDynamicSharedMemorySize, GP_SMEM);
    cudaFuncSetAttribute(gemm_pre<EPI_RELU2S>, cudaFuncAttributeMaxDynamicSharedMemorySize, GP_SMEM);

    // 0) convert weights to fp16
    {
        int n4w = CC * CC / 4;
        int n4f = MLPD * CC / 4;
        conv_fp16<<<(n4w + 255) / 256, 256>>>(wq, wq16, n4w);
        conv_fp16<<<(n4w + 255) / 256, 256>>>(wk, wk16, n4w);
        conv_fp16<<<(n4w + 255) / 256, 256>>>(wv, wv16, n4w);
        conv_fp16<<<(n4w + 255) / 256, 256>>>(wo, wo16, n4w);
        conv_fp16<<<(n4f + 255) / 256, 256>>>(fc1, fc116, n4f);
        conv_fp16<<<(n4f + 255) / 256, 256>>>(fc2, fc216, n4f);
    }

    // 1) h = rmsnorm(x)  (fp16 split)
    rmsnorm_split_kernel<<<BT, 256>>>(x, hH, hL);

    // 2-4) q,k,v = h @ w^T  (fp32 out for attention)
    dim3 thr(512);
    dim3 g_qkv(CC / 128, BT / 128);
    gemm_pre<EPI_F32><<<g_qkv, thr, GP_SMEM>>>(hH, hL, wq16, nullptr, q, nullptr, nullptr, BT, CC, CC);
    gemm_pre<EPI_F32><<<g_qkv, thr, GP_SMEM>>>(hH, hL, wk16, nullptr, k, nullptr, nullptr, BT, CC, CC);
    gemm_pre<EPI_F32><<<g_qkv, thr, GP_SMEM>>>(hH, hL, wv16, nullptr, v, nullptr, nullptr, BT, CC, CC);

    // 5) causal attention -> fp16 split att
    dim3 g_att_grid(TT / 64, HH, BB);
    attn_mma<<<g_att_grid, 128, ATT_SMEM>>>(q, k, v, attH, attL);

    // 6) x1 = x + att @ wo^T
    gemm_pre<EPI_ADDF><<<g_qkv, thr, GP_SMEM>>>(attH, attL, wo16, x, x1, nullptr, nullptr, BT, CC, CC);

    // 7) h = rmsnorm(x1)  (fp16 split)
    rmsnorm_split_kernel<<<BT, 256>>>(x1, hH, hL);

    // 8) m = relu(h @ fc1^T)^2  (fp16 split out)
    dim3 g_fc1(MLPD / 128, BT / 128);
    gemm_pre<EPI_RELU2S><<<g_fc1, thr, GP_SMEM>>>(hH, hL, fc116, nullptr, nullptr, mH, mL, BT, MLPD, CC);

    // 9) out = x1 + m @ fc2^T
    dim3 g_fc2(CC / 128, BT / 128);
    gemm_pre<EPI_ADDF><<<g_fc2, thr, GP_SMEM>>>(mH, mL, fc216, x1, out, nullptr, nullptr, BT, CC, MLPD);
}

// round 17
// speedup vs baseline: 1.9444x; 1.1065x over previous
#include <cuda_runtime.h>
#include <cuda_bf16.h>
#include <cuda_fp16.h>
#include <cstdint>
#include <stdint.h>
#include <math.h>

// Problem constants
#define BB 2
#define TT 2048
#define CC 2048
#define HH 16
#define HD 128
#define MLPD 8192
#define BT (BB*TT)          // 4096 rows
#define QKVS (3*CC)         // 6144, qkv row stride
#define EPS 1e-5f

// ---------------------------------------------------------------------------
// Scratch (device globals; no allocations allowed)
// ---------------------------------------------------------------------------
__device__ float g_x1[(size_t)BT*CC];

__device__ __half g_hH[(size_t)BT*CC],   g_hL[(size_t)BT*CC];
__device__ __half g_qkvH[(size_t)BT*QKVS], g_qkvL[(size_t)BT*QKVS];
__device__ __half g_attH[(size_t)BT*CC], g_attL[(size_t)BT*CC];
__device__ __half g_mH[(size_t)BT*MLPD], g_mL[(size_t)BT*MLPD];
__device__ __half g_wqkv16[(size_t)QKVS*CC];
__device__ __half g_wo16[(size_t)CC*CC];
__device__ __half g_fc1_16[(size_t)MLPD*CC];
__device__ __half g_fc2_16[(size_t)MLPD*CC];

// ---------------------------------------------------------------------------
// Helpers
// ---------------------------------------------------------------------------
union PackH4 { __half h[4]; uint2 u; };
union PackH8 { __half h[8]; uint4 u; };

__device__ __forceinline__ uint32_t smem_u32(const void* p) {
    uint32_t a;
    asm("{ .reg .u64 t; cvta.to.shared.u64 t, %1; cvt.u32.u64 %0, t; }" : "=r"(a) : "l"(p));
    return a;
}

__device__ __forceinline__ void cpasync16(uint32_t dst, const void* src) {
    asm volatile("cp.async.cg.shared.global [%0], [%1], 16;" :: "r"(dst), "l"(src));
}
#define CP_COMMIT() asm volatile("cp.async.commit_group;" ::: "memory")
#define CP_WAIT(n)  asm volatile("cp.async.wait_group %0;" :: "n"(n) : "memory")

#define MMA_FP16(d, a, b0v, b1v)                                           \
    asm volatile("mma.sync.aligned.m16n8k16.row.col.f32.f16.f16.f32 "      \
        "{%0,%1,%2,%3}, {%4,%5,%6,%7}, {%8,%9}, {%0,%1,%2,%3};"            \
        : "+f"(d[0]), "+f"(d[1]), "+f"(d[2]), "+f"(d[3])                   \
        : "r"(a[0]), "r"(a[1]), "r"(a[2]), "r"(a[3]), "r"(b0v), "r"(b1v))

// fp16 hi/lo pack
__device__ __forceinline__ void split_pack2h(float x, float y,
                                             unsigned int& hi, unsigned int& lo) {
    __half xh = __float2half_rn(x);
    __half yh = __float2half_rn(y);
    __half xl = __float2half_rn(x - __half2float(xh));
    __half yl = __float2half_rn(y - __half2float(yh));
    hi = (unsigned int)__half_as_ushort(xh) |
         ((unsigned int)__half_as_ushort(yh) << 16);
    lo = (unsigned int)__half_as_ushort(xl) |
         ((unsigned int)__half_as_ushort(yl) << 16);
}

// ---------------------------------------------------------------------------
// Weight conversion fp32 -> fp16 (optional scale folded in)
// ---------------------------------------------------------------------------
__global__ void conv_fp16(const float* __restrict__ in,
                          __half* __restrict__ H, int n4, float scale) {
    int i = blockIdx.x * blockDim.x + threadIdx.x;
    if (i >= n4) return;
    float4 v = reinterpret_cast<const float4*>(in)[i];
    PackH4 Hp;
    Hp.h[0] = __float2half_rn(v.x * scale);
    Hp.h[1] = __float2half_rn(v.y * scale);
    Hp.h[2] = __float2half_rn(v.z * scale);
    Hp.h[3] = __float2half_rn(v.w * scale);
    reinterpret_cast<uint2*>(H)[i] = Hp.u;
}

// ---------------------------------------------------------------------------
// RMSNorm with fp16 split epilogue
// ---------------------------------------------------------------------------
__global__ void rmsnorm_split_kernel(const float* __restrict__ x,
                                     __half* __restrict__ H,
                                     __half* __restrict__ L) {
    int row = blockIdx.x;
    const float* xr = x + (size_t)row * CC;
    float ss = 0.f;
    for (int c = threadIdx.x; c < CC; c += blockDim.x) {
        float vv = xr[c];
        ss += vv * vv;
    }
    __shared__ float red[32];
    #pragma unroll
    for (int off = 16; off; off >>= 1) ss += __shfl_xor_sync(0xffffffffu, ss, off);
    int wid = threadIdx.x >> 5, lane = threadIdx.x & 31;
    if (lane == 0) red[wid] = ss;
    __syncthreads();
    if (wid == 0) {
        float v2 = lane < (blockDim.x >> 5) ? red[lane] : 0.f;
        #pragma unroll
        for (int off = 16; off; off >>= 1) v2 += __shfl_xor_sync(0xffffffffu, v2, off);
        if (lane == 0) red[0] = rsqrtf(v2 / (float)CC + EPS);
    }
    __syncthreads();
    float r = red[0];
    size_t base = (size_t)row * CC;
    for (int c = threadIdx.x * 2; c < CC; c += blockDim.x * 2) {
        float a = xr[c] * r, b = xr[c + 1] * r;
        unsigned int hi, lo;
        split_pack2h(a, b, hi, lo);
        *reinterpret_cast<unsigned int*>(&H[base + c]) = hi;
        *reinterpret_cast<unsigned int*>(&L[base + c]) = lo;
    }
}

// ---------------------------------------------------------------------------
// fp16x2 GEMM: C = (AH+AL)[M,K] @ W[N,K]^T, cp.async 3-stage pipeline.
// Block 128x128x32, 512 threads, warp tile 32x32 (proven R16 structure).
// ---------------------------------------------------------------------------
enum { EPI_ADDF = 1, EPI_RELU2S = 2, EPI_SPLITH = 3 };

#define GP_PART   10240              // bytes per part (128 rows x 80B pitch)
#define GP_STAGE  (3*GP_PART)        // AH, AL, W
#define GP_NSTG   3
#define GP_SMEM   (GP_NSTG*GP_STAGE) // 92160 bytes

__device__ __forceinline__ void gp_issue(
    uint32_t sb32, int buf, int tid,
    const __half* __restrict__ AH, const __half* __restrict__ AL,
    const __half* __restrict__ W,
    int bm, int bn, int K, int k0)
{
    int row = tid >> 2, c = tid & 3;
    size_t offA = (size_t)(bm + row) * K + k0 + c * 8;
    size_t offB = (size_t)(bn + row) * K + k0 + c * 8;
    uint32_t d = sb32 + buf * GP_STAGE + row * 80 + c * 16;
    cpasync16(d,               AH + offA);
    cpasync16(d + GP_PART,     AL + offA);
    cpasync16(d + 2 * GP_PART, W + offB);
}

template <int EPI>
__global__ __launch_bounds__(512, 1) void gemm_pre(
    const __half* __restrict__ AH, const __half* __restrict__ AL,
    const __half* __restrict__ W,
    const float* __restrict__ Res, float* __restrict__ C,
    __half* __restrict__ CH, __half* __restrict__ CL,
    int M, int N, int K)
{
    extern __shared__ char smp[];
    uint32_t sb32 = smem_u32(smp);
    int tid = threadIdx.x;
    int bm = blockIdx.y * 128;
    int bn = blockIdx.x * 128;
    int wid = tid >> 5, lane = tid & 31;
    int wm = (wid & 3) * 32;
    int wn = (wid >> 2) * 32;
    int lt = lane >> 2, g = lane & 3;

    float acc[2][4][4];
    #pragma unroll
    for (int i = 0; i < 2; i++)
        #pragma unroll
        for (int j = 0; j < 4; j++)
            #pragma unroll
            for (int r = 0; r < 4; r++) acc[i][j][r] = 0.f;

    int nst = K / 32;
    #pragma unroll
    for (int p = 0; p < 2; p++) {
        gp_issue(sb32, p, tid, AH, AL, W, bm, bn, K, p * 32);
        CP_COMMIT();
    }

    for (int it = 0; it < nst; it++) {
        if (it + 1 < nst) { CP_WAIT(1); } else { CP_WAIT(0); }
        __syncthreads();

        int b = it - (it / 3) * 3;   // it % 3
        const unsigned int* base =
            reinterpret_cast<const unsigned int*>(smp + b * GP_STAGE);
        const unsigned int* AHw = base;
        const unsigned int* ALw = base + 2560;
        const unsigned int* Ww  = base + 5120;

        #pragma unroll
        for (int kk2 = 0; kk2 < 2; kk2++) {
            int kw = kk2 * 8;
            unsigned int ah[2][4], al[2][4];
            #pragma unroll
            for (int mi = 0; mi < 2; mi++) {
                int m0 = wm + mi * 16 + lt;
                int base0 = m0 * 20 + kw + g;
                int base1 = (m0 + 8) * 20 + kw + g;
                ah[mi][0] = AHw[base0];
                ah[mi][1] = AHw[base1];
                ah[mi][2] = AHw[base0 + 4];
                ah[mi][3] = AHw[base1 + 4];
                al[mi][0] = ALw[base0];
                al[mi][1] = ALw[base1];
                al[mi][2] = ALw[base0 + 4];
                al[mi][3] = ALw[base1 + 4];
            }
            #pragma unroll
            for (int ni = 0; ni < 4; ni++) {
                int n0 = wn + ni * 8 + lt;
                int nb = n0 * 20 + kw + g;
                unsigned int b0 = Ww[nb], b1 = Ww[nb + 4];
                #pragma unroll
                for (int mi = 0; mi < 2; mi++) {
                    MMA_FP16(acc[mi][ni], ah[mi], b0, b1);
                    MMA_FP16(acc[mi][ni], al[mi], b0, b1);
                }
            }
        }

        if (it + 2 < nst) {
            int nb3 = (it + 2) - ((it + 2) / 3) * 3;
            gp_issue(sb32, nb3, tid, AH, AL, W, bm, bn, K, (it + 2) * 32);
            CP_COMMIT();
        }
    }

    // epilogue
    #pragma unroll
    for (int mi = 0; mi < 2; mi++) {
        #pragma unroll
        for (int ni = 0; ni < 4; ni++) {
            int r0 = bm + wm + mi * 16 + lt;
            int c0 = bn + wn + ni * 8 + g * 2;
            float2 v0 = {acc[mi][ni][0], acc[mi][ni][1]};
            float2 v1 = {acc[mi][ni][2], acc[mi][ni][3]};
            if (EPI == EPI_RELU2S || EPI == EPI_SPLITH) {
                if (EPI == EPI_RELU2S) {
                    v0.x = fmaxf(v0.x, 0.f); v0.x *= v0.x;
                    v0.y = fmaxf(v0.y, 0.f); v0.y *= v0.y;
                    v1.x = fmaxf(v1.x, 0.f); v1.x *= v1.x;
                    v1.y = fmaxf(v1.y, 0.f); v1.y *= v1.y;
                }
                unsigned int h0, l0, h1, l1;
                split_pack2h(v0.x, v0.y, h0, l0);
                split_pack2h(v1.x, v1.y, h1, l1);
                *reinterpret_cast<unsigned int*>(&CH[(size_t)r0 * N + c0]) = h0;
                *reinterpret_cast<unsigned int*>(&CL[(size_t)r0 * N + c0]) = l0;
                *reinterpret_cast<unsigned int*>(&CH[(size_t)(r0 + 8) * N + c0]) = h1;
                *reinterpret_cast<unsigned int*>(&CL[(size_t)(r0 + 8) * N + c0]) = l1;
            } else {
                float2 r0v = *reinterpret_cast<const float2*>(&Res[(size_t)r0 * N + c0]);
                float2 r1v = *reinterpret_cast<const float2*>(&Res[(size_t)(r0 + 8) * N + c0]);
                v0.x += r0v.x; v0.y += r0v.y;
                v1.x += r1v.x; v1.y += r1v.y;
                *reinterpret_cast<float2*>(&C[(size_t)r0 * N + c0]) = v0;
                *reinterpret_cast<float2*>(&C[(size_t)(r0 + 8) * N + c0]) = v1;
            }
        }
    }
}

// ---------------------------------------------------------------------------
// fp16x2 flash attention. Inputs: pre-split fp16 qkv (Q pre-scaled via wq).
// S = (qH+qL)·kH (2 MMAs), PV = (pH+pL)·vH (2 MMAs).
// smem: QH, QL, KH [64][136] fp16; Vt [128][72] fp16.
// ---------------------------------------------------------------------------
#define SQH 0
#define SQL 8704      // 64*136
#define SKH 17408
#define SVT 26112     // 128 rows * 72
#define ATT_SMEM 70656   // (26112 + 9216) * 2 bytes
// word offsets (uint32)
#define WQHo 0
#define WQLo 4352
#define WKHo 8704
#define WVTo 13056

__global__ __launch_bounds__(128) void attn_mma(
    const __half* __restrict__ qkvH, const __half* __restrict__ qkvL,
    __half* __restrict__ oH, __half* __restrict__ oL)
{
    extern __shared__ char attsm[];
    __half* sh = reinterpret_cast<__half*>(attsm);
    unsigned int* s32 = reinterpret_cast<unsigned int*>(attsm);

    int tid = threadIdx.x;
    int wid = tid >> 5, lane = tid & 31;
    int lt = lane >> 2, g = lane & 3;
    int wrow = wid * 16;
    int qt = blockIdx.x, h = blockIdx.y, b = blockIdx.z;
    int qb = qt * 64;
    size_t rowbase = (size_t)b * TT;   // token row offset
    int hcol = h * HD;

    // ---- load Q hi+lo (pure copy, 8 fp16 per uint4) ----
    #pragma unroll
    for (int i = 0; i < 8; i++) {
        int lin = tid + i * 128;
        int r = lin >> 4, c8 = (lin & 15) * 8;
        size_t src = (rowbase + qb + r) * QKVS + hcol + c8;
        *reinterpret_cast<uint4*>(&sh[SQH + r * 136 + c8]) =
            *reinterpret_cast<const uint4*>(&qkvH[src]);
        *reinterpret_cast<uint4*>(&sh[SQL + r * 136 + c8]) =
            *reinterpret_cast<const uint4*>(&qkvL[src]);
    }

    float oacc[16][4];
    #pragma unroll
    for (int i = 0; i < 16; i++)
        #pragma unroll
        for (int j = 0; j < 4; j++) oacc[i][j] = 0.f;
    float m0 = -1e30f, m1 = -1e30f, l0 = 0.f, l1 = 0.f;

    for (int nt = 0; nt <= qt; nt++) {
        int kb = nt * 64;
        // ---- load K hi (copy) ----
        #pragma unroll
        for (int i = 0; i < 8; i++) {
            int lin = tid + i * 128;
            int r = lin >> 4, c8 = (lin & 15) * 8;
            size_t src = (rowbase + kb + r) * QKVS + CC + hcol + c8;
            *reinterpret_cast<uint4*>(&sh[SKH + r * 136 + c8]) =
                *reinterpret_cast<const uint4*>(&qkvH[src]);
        }
        // ---- load V hi transposed: Vt[d][token] ----
        #pragma unroll
        for (int i = 0; i < 8; i++) {
            int lin = tid + i * 128;
            int r = lin & 63;                 // token
            int c8 = (lin >> 6) * 8;          // d chunk (0..15)*8
            size_t src = (rowbase + kb + r) * QKVS + 2 * CC + hcol + c8;
            PackH8 vv;
            vv.u = *reinterpret_cast<const uint4*>(&qkvH[src]);
            #pragma unroll
            for (int j = 0; j < 8; j++)
                sh[SVT + (c8 + j) * 72 + r] = vv.h[j];
        }
        __syncthreads();

        // ---- S = Q K^T (fp16 2-term) ----
        float sacc[8][4];
        #pragma unroll
        for (int i = 0; i < 8; i++)
            #pragma unroll
            for (int j = 0; j < 4; j++) sacc[i][j] = 0.f;

        #pragma unroll
        for (int ks = 0; ks < 8; ks++) {
            unsigned int aH[4], aL[4];
            int ab = (wrow + lt) * 68 + ks * 8 + g;
            aH[0] = s32[WQHo + ab];       aH[1] = s32[WQHo + ab + 544];
            aH[2] = s32[WQHo + ab + 4];   aH[3] = s32[WQHo + ab + 548];
            aL[0] = s32[WQLo + ab];       aL[1] = s32[WQLo + ab + 544];
            aL[2] = s32[WQLo + ab + 4];   aL[3] = s32[WQLo + ab + 548];
            #pragma unroll
            for (int ni = 0; ni < 8; ni++) {
                int bb = (ni * 8 + lt) * 68 + ks * 8 + g;
                unsigned int b0 = s32[WKHo + bb], b1 = s32[WKHo + bb + 4];
                MMA_FP16(sacc[ni], aH, b0, b1);
                MMA_FP16(sacc[ni], aL, b0, b1);
            }
        }

        // ---- causal mask (diagonal tile only) ----
        if (nt == qt) {
            int row0 = qb + wrow + lt, row1 = row0 + 8;
            #pragma unroll
            for (int ni = 0; ni < 8; ni++) {
                int c0 = kb + ni * 8 + 2 * g;
                if (c0 > row0)     sacc[ni][0] = -1e30f;
                if (c0 + 1 > row0) sacc[ni][1] = -1e30f;
                if (c0 > row1)     sacc[ni][2] = -1e30f;
                if (c0 + 1 > row1) sacc[ni][3] = -1e30f;
            }
        }

        // ---- online softmax (registers) ----
        float rm0 = -1e30f, rm1 = -1e30f;
        #pragma unroll
        for (int ni = 0; ni < 8; ni++) {
            rm0 = fmaxf(rm0, fmaxf(sacc[ni][0], sacc[ni][1]));
            rm1 = fmaxf(rm1, fmaxf(sacc[ni][2], sacc[ni][3]));
        }
        rm0 = fmaxf(rm0, __shfl_xor_sync(0xffffffffu, rm0, 1));
        rm0 = fmaxf(rm0, __shfl_xor_sync(0xffffffffu, rm0, 2));
        rm1 = fmaxf(rm1, __shfl_xor_sync(0xffffffffu, rm1, 1));
        rm1 = fmaxf(rm1, __shfl_xor_sync(0xffffffffu, rm1, 2));
        float mn0 = fmaxf(m0, rm0), mn1 = fmaxf(m1, rm1);
        float al0 = __expf(m0 - mn0), al1 = __expf(m1 - mn1);
        m0 = mn0; m1 = mn1;
        float rs0 = 0.f, rs1 = 0.f;
        #pragma unroll
        for (int ni = 0; ni < 8; ni++) {
            sacc[ni][0] = __expf(sacc[ni][0] - m0);
            sacc[ni][1] = __expf(sacc[ni][1] - m0);
            sacc[ni][2] = __expf(sacc[ni][2] - m1);
            sacc[ni][3] = __expf(sacc[ni][3] - m1);
            rs0 += sacc[ni][0] + sacc[ni][1];
            rs1 += sacc[ni][2] + sacc[ni][3];
        }
        l0 = l0 * al0 + rs0;
        l1 = l1 * al1 + rs1;
        #pragma unroll
        for (int ni = 0; ni < 16; ni++) {
            oacc[ni][0] *= al0; oacc[ni][1] *= al0;
            oacc[ni][2] *= al1; oacc[ni][3] *= al1;
        }

        // ---- O += P V (fp16 2-term; P split from registers) ----
        #pragma unroll
        for (int kk = 0; kk < 4; kk++) {
            unsigned int pH[4], pL[4];
            split_pack2h(sacc[2 * kk][0],     sacc[2 * kk][1],     pH[0], pL[0]);
            split_pack2h(sacc[2 * kk][2],     sacc[2 * kk][3],     pH[1], pL[1]);
            split_pack2h(sacc[2 * kk + 1][0], sacc[2 * kk + 1][1], pH[2], pL[2]);
            split_pack2h(sacc[2 * kk + 1][2], sacc[2 * kk + 1][3], pH[3], pL[3]);
            #pragma unroll
            for (int ni = 0; ni < 16; ni++) {
                int vb2 = (ni * 8 + lt) * 36 + kk * 8 + g;
                unsigned int v0 = s32[WVTo + vb2], v1 = s32[WVTo + vb2 + 4];
                MMA_FP16(oacc[ni], pH, v0, v1);
                MMA_FP16(oacc[ni], pL, v0, v1);
            }
        }
        __syncthreads();
    }

    // ---- finalize ----
    l0 += __shfl_xor_sync(0xffffffffu, l0, 1);
    l0 += __shfl_xor_sync(0xffffffffu, l0, 2);
    l1 += __shfl_xor_sync(0xffffffffu, l1, 1);
    l1 += __shfl_xor_sync(0xffffffffu, l1, 2);
    float inv0 = 1.f / l0, inv1 = 1.f / l1;
    int row0 = qb + wrow + lt;
    #pragma unroll
    for (int ni = 0; ni < 16; ni++) {
        size_t o0 = ((size_t)(rowbase + row0)) * CC + hcol + ni * 8 + 2 * g;
        size_t o1 = o0 + (size_t)8 * CC;
        unsigned int h0, l0u, h1, l1u;
        split_pack2h(oacc[ni][0] * inv0, oacc[ni][1] * inv0, h0, l0u);
        split_pack2h(oacc[ni][2] * inv1, oacc[ni][3] * inv1, h1, l1u);
        *reinterpret_cast<unsigned int*>(&oH[o0]) = h0;
        *reinterpret_cast<unsigned int*>(&oL[o0]) = l0u;
        *reinterpret_cast<unsigned int*>(&oH[o1]) = h1;
        *reinterpret_cast<unsigned int*>(&oL[o1]) = l1u;
    }
}

// ---------------------------------------------------------------------------
// Launch
// ---------------------------------------------------------------------------
extern "C" void kernel_launch(void* const* d_in, const int* in_sizes, int n_in,
                              void* d_out, int out_size) {
    const float* x   = (const float*)d_in[0];
    const float* wq  = (const float*)d_in[1];
    const float* wk  = (const float*)d_in[2];
    const float* wv  = (const float*)d_in[3];
    const float* wo  = (const float*)d_in[4];
    const float* fc1 = (const float*)d_in[5];
    const float* fc2 = (const float*)d_in[6];
    float* out = (float*)d_out;

    float *x1;
    cudaGetSymbolAddress((void**)&x1, g_x1);

    __half *hH, *hL, *qkvH, *qkvL, *attH, *attL, *mH, *mL;
    __half *wqkv16, *wo16, *fc116, *fc216;
    cudaGetSymbolAddress((void**)&hH, g_hH);     cudaGetSymbolAddress((void**)&hL, g_hL);
    cudaGetSymbolAddress((void**)&qkvH, g_qkvH); cudaGetSymbolAddress((void**)&qkvL, g_qkvL);
    cudaGetSymbolAddress((void**)&attH, g_attH); cudaGetSymbolAddress((void**)&attL, g_attL);
    cudaGetSymbolAddress((void**)&mH, g_mH);     cudaGetSymbolAddress((void**)&mL, g_mL);
    cudaGetSymbolAddress((void**)&wqkv16, g_wqkv16);
    cudaGetSymbolAddress((void**)&wo16, g_wo16);
    cudaGetSymbolAddress((void**)&fc116, g_fc1_16);
    cudaGetSymbolAddress((void**)&fc216, g_fc2_16);

    cudaFuncSetAttribute(attn_mma, cudaFuncAttributeMaxDynamicSharedMemorySize, ATT_SMEM);
    cudaFuncSetAttribute(gemm_pre<EPI_ADDF>,   cudaFuncAttributeMaxDynamicSharedMemorySize, GP_SMEM);
    cudaFuncSetAttribute(gemm_pre<EPI_RELU2S>, cudaFuncAttributeMaxDynamicSharedMemorySize, GP_SMEM);
    cudaFuncSetAttribute(gemm_pre<EPI_SPLITH>, cudaFuncAttributeMaxDynamicSharedMemorySize, GP_SMEM);

    const float qscale = 0.08838834764831845f;  // 1/sqrt(HD)

    // 0) convert weights to fp16 (wq scaled; packed into one qkv buffer)
    {
        int n4w = CC * CC / 4;
        int n4f = MLPD * CC / 4;
        conv_fp16<<<(n4w + 255) / 256, 256>>>(wq, wqkv16,                    n4w, qscale);
        conv_fp16<<<(n4w + 255) / 256, 256>>>(wk, wqkv16 + (size_t)CC * CC,  n4w, 1.f);
        conv_fp16<<<(n4w + 255) / 256, 256>>>(wv, wqkv16 + (size_t)2*CC*CC,  n4w, 1.f);
        conv_fp16<<<(n4w + 255) / 256, 256>>>(wo, wo16,  n4w, 1.f);
        conv_fp16<<<(n4f + 255) / 256, 256>>>(fc1, fc116, n4f, 1.f);
        conv_fp16<<<(n4f + 255) / 256, 256>>>(fc2, fc216, n4f, 1.f);
    }

    // 1) h = rmsnorm(x)  (fp16 split)
    rmsnorm_split_kernel<<<BT, 256>>>(x, hH, hL);

    // 2) qkv = h @ [wq*s; wk; wv]^T  (fp16 split out, one wide GEMM)
    dim3 thr(512);
    dim3 g_qkv(QKVS / 128, BT / 128);
    gemm_pre<EPI_SPLITH><<<g_qkv, thr, GP_SMEM>>>(hH, hL, wqkv16, nullptr, nullptr,
                                                  qkvH, qkvL, BT, QKVS, CC);

    // 3) causal attention -> fp16 split att
    dim3 g_att_grid(TT / 64, HH, BB);
    attn_mma<<<g_att_grid, 128, ATT_SMEM>>>(qkvH, qkvL, attH, attL);

    // 4) x1 = x + att @ wo^T
    dim3 g_sq(CC / 128, BT / 128);
    gemm_pre<EPI_ADDF><<<g_sq, thr, GP_SMEM>>>(attH, attL, wo16, x, x1,
                                               nullptr, nullptr, BT, CC, CC);

    // 5) h = rmsnorm(x1)  (fp16 split)
    rmsnorm_split_kernel<<<BT, 256>>>(x1, hH, hL);

    // 6) m = relu(h @ fc1^T)^2  (fp16 split out)
    dim3 g_fc1(MLPD / 128, BT / 128);
    gemm_pre<EPI_RELU2S><<<g_fc1, thr, GP_SMEM>>>(hH, hL, fc116, nullptr, nullptr,
                                                  mH, mL, BT, MLPD, CC);

    // 7) out = x1 + m @ fc2^T
    dim3 g_fc2(CC / 128, BT / 128);
    gemm_pre<EPI_ADDF><<<g_fc2, thr, GP_SMEM>>>(mH, mL, fc216, x1, out,
                                                nullptr, nullptr, BT, CC, MLPD);
}